// round 1
// baseline (speedup 1.0000x reference)
#include <cuda_runtime.h>
#include <cuda_bf16.h>
#include <math.h>

// Problem dims
#define N_ATOMS 50000
#define N_PAIRS 800000
#define N_EMB   128
#define N_DIST  100
#define N_HID   128

// Device scratch (no cudaMalloc allowed)
__device__ float g_afh[(size_t)N_ATOMS * N_HID];          // 25.6 MB
__device__ float g_msg[(size_t)N_PAIRS * N_HID];          // 409.6 MB

// ----------------------------------------------------------------------------
// Generic 128x128 register-tiled fp32 GEMM with fused epilogues.
//   C_tile = A[M,KDIM] @ B[KDIM,128]   (A row stride = KDIM, B row stride = 128)
// MODE 0: C[m][n] = acc + bvec[n]                                   (afh)
// MODE 1: C[m][n] = aux[m][n] - tanh(acc), A scaled by ascale[k]    (out init)
// MODE 2: C[m][n] = (acc + bvec[n]) * aux[idx[m]][n]                (msgs)
// MODE 3: atomicAdd(&C[idx[m]][n], tanh(acc))                       (segment sum)
// ----------------------------------------------------------------------------
constexpr int BM = 128, BN = 128, BK = 8, TM = 8, TN = 8;

template <int KDIM, int MODE>
__launch_bounds__(256, 2)
__global__ void gemm_k(const float* __restrict__ A,
                       const float* __restrict__ B,
                       const float* __restrict__ bvec,
                       const float* __restrict__ ascale,
                       const float* __restrict__ aux,
                       const int*   __restrict__ idx,
                       float* __restrict__ C,
                       int M)
{
    __shared__ float As[BK][BM];
    __shared__ float Bs[BK][BN];

    const int tid = threadIdx.x;
    const int tx  = tid % 16;          // column group (8 cols each)
    const int ty  = tid / 16;          // row group (8 rows each)
    const int m0  = blockIdx.x * BM;

    float acc[TM][TN];
#pragma unroll
    for (int i = 0; i < TM; i++)
#pragma unroll
        for (int j = 0; j < TN; j++) acc[i][j] = 0.0f;

    // A-load mapping: 4 consecutive k per thread (BM*BK = 1024 = 256*4)
    const int a_row  = tid / 2;              // 0..127
    const int a_col0 = (tid % 2) * 4;        // 0 or 4
    // B-load mapping: one float4 per thread (BK*BN = 1024)
    const int b_row  = tid / 32;             // 0..7
    const int b_col  = (tid % 32) * 4;       // 0..124

    for (int k0 = 0; k0 < KDIM; k0 += BK) {
        // ---- stage A tile (guarded; scale for MODE 1) ----
        {
            const int gm = m0 + a_row;
#pragma unroll
            for (int u = 0; u < 4; u++) {
                const int gk = k0 + a_col0 + u;
                float v = 0.0f;
                if (gm < M && gk < KDIM) {
                    v = A[(size_t)gm * KDIM + gk];
                    if (MODE == 1) v *= ascale[gk];
                }
                As[a_col0 + u][a_row] = v;
            }
        }
        // ---- stage B tile (float4, guarded on k) ----
        {
            const int gk = k0 + b_row;
            float4 v = make_float4(0.f, 0.f, 0.f, 0.f);
            if (gk < KDIM)
                v = *reinterpret_cast<const float4*>(&B[(size_t)gk * BN + b_col]);
            *reinterpret_cast<float4*>(&Bs[b_row][b_col]) = v;
        }
        __syncthreads();

        // ---- MACs ----
#pragma unroll
        for (int kk = 0; kk < BK; kk++) {
            float af[TM], bf[TN];
#pragma unroll
            for (int i = 0; i < TM; i++) af[i] = As[kk][ty * TM + i];
#pragma unroll
            for (int j = 0; j < TN; j++) bf[j] = Bs[kk][tx * TN + j];
#pragma unroll
            for (int i = 0; i < TM; i++)
#pragma unroll
                for (int j = 0; j < TN; j++) acc[i][j] = fmaf(af[i], bf[j], acc[i][j]);
        }
        __syncthreads();
    }

    // ---- epilogue ----
#pragma unroll
    for (int i = 0; i < TM; i++) {
        const int m = m0 + ty * TM + i;
        if (m >= M) continue;

        if (MODE == 0) {
#pragma unroll
            for (int j = 0; j < TN; j++) {
                const int n = tx * TN + j;
                C[(size_t)m * BN + n] = acc[i][j] + bvec[n];
            }
        } else if (MODE == 1) {
#pragma unroll
            for (int j = 0; j < TN; j++) {
                const int n = tx * TN + j;
                C[(size_t)m * BN + n] = aux[(size_t)m * BN + n] - tanhf(acc[i][j]);
            }
        } else if (MODE == 2) {
            const int jrow = idx[m];
            const float* arow = aux + (size_t)jrow * BN;
#pragma unroll
            for (int j = 0; j < TN; j++) {
                const int n = tx * TN + j;
                C[(size_t)m * BN + n] = (acc[i][j] + bvec[n]) * arow[n];
            }
        } else { // MODE 3
            const int irow = idx[m];
            float* crow = C + (size_t)irow * BN;
#pragma unroll
            for (int j = 0; j < TN; j++) {
                const int n = tx * TN + j;
                atomicAdd(&crow[n], tanhf(acc[i][j]));
            }
        }
    }
}

extern "C" void kernel_launch(void* const* d_in, const int* in_sizes, int n_in,
                              void* d_out, int out_size)
{
    const float* atom_features = (const float*)d_in[0];
    const float* distance      = (const float*)d_in[1];
    // d_in[2] = atom_membership (unused by the reference computation)
    const int*   dmi           = (const int*)d_in[3];
    const int*   dmj           = (const int*)d_in[4];
    const float* W_cf          = (const float*)d_in[5];
    const float* W_df          = (const float*)d_in[6];
    const float* W_fc          = (const float*)d_in[7];
    const float* b_cf          = (const float*)d_in[8];
    const float* b_df          = (const float*)d_in[9];
    float* out = (float*)d_out;

    float* afh = nullptr;
    float* msg = nullptr;
    cudaGetSymbolAddress((void**)&afh, g_afh);
    cudaGetSymbolAddress((void**)&msg, g_msg);

    const int atom_blocks = (N_ATOMS + BM - 1) / BM;   // 391
    const int pair_blocks = (N_PAIRS + BM - 1) / BM;   // 6250

    // K1: afh = atom_features @ W_cf + b_cf
    gemm_k<N_EMB, 0><<<atom_blocks, 256>>>(atom_features, W_cf, b_cf,
                                           nullptr, nullptr, nullptr,
                                           afh, N_ATOMS);
    // K2: out = atom_features - tanh((b_df * afh) @ W_fc)
    gemm_k<N_HID, 1><<<atom_blocks, 256>>>(afh, W_fc, nullptr,
                                           b_df, atom_features, nullptr,
                                           out, N_ATOMS);
    // K3: msg = (distance @ W_df + b_df) * afh[dmj]
    gemm_k<N_DIST, 2><<<pair_blocks, 256>>>(distance, W_df, b_df,
                                            nullptr, afh, dmj,
                                            msg, N_PAIRS);
    // K4: out[dmi] += tanh(msg @ W_fc)
    gemm_k<N_HID, 3><<<pair_blocks, 256>>>(msg, W_fc, nullptr,
                                           nullptr, nullptr, dmi,
                                           out, N_PAIRS);
}

// round 9
// speedup vs baseline: 2.7773x; 2.7773x over previous
#include <cuda_runtime.h>
#include <cuda_bf16.h>
#include <cstdint>
#include <math.h>

#define N_ATOMS 50000
#define N_PAIRS 800000

// ---------------------------------------------------------------------------
// Device scratch (no cudaMalloc allowed)
// ---------------------------------------------------------------------------
__device__ float g_afh[(size_t)N_ATOMS * 128];   // 25.6 MB, L2-resident

// ---------------------------------------------------------------------------
// SMEM layout (dynamic): all bf16 tiles padded to PK=136 cols (272B rows ->
// conflict-free ldmatrix across 8-row strides).
// ---------------------------------------------------------------------------
constexpr int PK = 136;
constexpr int TILE_B = 128 * PK * 2;            // 34816 B per bf16 tile
constexpr int OFF_B1H = 0;
constexpr int OFF_B1L = TILE_B;
constexpr int OFF_B2H = 2 * TILE_B;
constexpr int OFF_B2L = 3 * TILE_B;
constexpr int OFF_AH  = 4 * TILE_B;             // 139264 (union w/ out-tile fp32)
constexpr int OFF_AL  = OFF_AH + TILE_B;        // 174080
constexpr int OFF_IDX = OFF_AH + 2 * TILE_B;    // 208896
constexpr int SMEM_SZ = OFF_IDX + 1024;         // 209920
constexpr int OUT_STRIDE = 132;                 // fp32 out-tile padded stride

// ---------------------------------------------------------------------------
// PTX primitives (baseline ISA: sm_80+, compiles for plain sm_103)
// ---------------------------------------------------------------------------
__device__ __forceinline__ uint32_t smem_to_u32(const void* p) {
    uint32_t a;
    asm("{ .reg .u64 t; cvta.to.shared.u64 t, %1; cvt.u32.u64 %0, t; }" : "=r"(a) : "l"(p));
    return a;
}

__device__ __forceinline__ void ldsm_x4(uint32_t (&r)[4], uint32_t addr) {
    asm volatile("ldmatrix.sync.aligned.m8n8.x4.shared.b16 {%0,%1,%2,%3}, [%4];"
                 : "=r"(r[0]), "=r"(r[1]), "=r"(r[2]), "=r"(r[3]) : "r"(addr));
}
__device__ __forceinline__ void ldsm_x4_t(uint32_t (&r)[4], uint32_t addr) {
    asm volatile("ldmatrix.sync.aligned.m8n8.x4.trans.shared.b16 {%0,%1,%2,%3}, [%4];"
                 : "=r"(r[0]), "=r"(r[1]), "=r"(r[2]), "=r"(r[3]) : "r"(addr));
}
__device__ __forceinline__ void mma_bf16(float (&c)[4], const uint32_t (&a)[4],
                                         uint32_t b0, uint32_t b1) {
    asm volatile(
        "mma.sync.aligned.m16n8k16.row.col.f32.bf16.bf16.f32 "
        "{%0,%1,%2,%3}, {%4,%5,%6,%7}, {%8,%9}, {%0,%1,%2,%3};"
        : "+f"(c[0]), "+f"(c[1]), "+f"(c[2]), "+f"(c[3])
        : "r"(a[0]), "r"(a[1]), "r"(a[2]), "r"(a[3]), "r"(b0), "r"(b1));
}

// ---------------------------------------------------------------------------
// Helpers
// ---------------------------------------------------------------------------
__device__ __forceinline__ void split_pack(float a, float b, uint32_t& hi, uint32_t& lo) {
    __nv_bfloat162 h2 = __floats2bfloat162_rn(a, b);
    float2 hf = __bfloat1622float2(h2);
    __nv_bfloat162 l2 = __floats2bfloat162_rn(a - hf.x, b - hf.y);
    hi = *reinterpret_cast<uint32_t*>(&h2);
    lo = *reinterpret_cast<uint32_t*>(&l2);
}

__device__ __forceinline__ float tanh_fast(float x) {
    float e = __expf(2.0f * x);
    return 1.0f - __fdividef(2.0f, e + 1.0f);
}

// GEMM over 16 n-tiles: two A halves share each B fragment load.
__device__ __forceinline__ void run_gemm_dual(float (&acc)[16][4], uint32_t aH,
                                              uint32_t aL, uint32_t bA, int ksteps) {
    for (int kk = 0; kk < ksteps; kk++) {
        uint32_t ah[4], al[4];
        ldsm_x4(ah, aH);
        ldsm_x4(al, aL);
#pragma unroll
        for (int j2 = 0; j2 < 8; j2++) {
            uint32_t b[4];
            ldsm_x4_t(b, bA + j2 * 32);
            mma_bf16(acc[2 * j2],     ah, b[0], b[1]);
            mma_bf16(acc[2 * j2 + 1], ah, b[2], b[3]);
            mma_bf16(acc[2 * j2],     al, b[0], b[1]);
            mma_bf16(acc[2 * j2 + 1], al, b[2], b[3]);
        }
        aH += 32; aL += 32; bA += 16 * PK * 2;
    }
}

__device__ __forceinline__ void run_gemm_one(float (&acc)[16][4], uint32_t aA,
                                             uint32_t bA, int ksteps) {
    for (int kk = 0; kk < ksteps; kk++) {
        uint32_t a[4];
        ldsm_x4(a, aA);
#pragma unroll
        for (int j2 = 0; j2 < 8; j2++) {
            uint32_t b[4];
            ldsm_x4_t(b, bA + j2 * 32);
            mma_bf16(acc[2 * j2],     a, b[0], b[1]);
            mma_bf16(acc[2 * j2 + 1], a, b[2], b[3]);
        }
        aA += 32; bA += 16 * PK * 2;
    }
}

__device__ __forceinline__ void run_gemm_regA_dual(float (&acc)[16][4],
                                                   const uint32_t (&ah)[8][4],
                                                   const uint32_t (&al)[8][4],
                                                   uint32_t bA) {
#pragma unroll
    for (int kk = 0; kk < 8; kk++) {
        uint32_t bk = bA + kk * (16 * PK * 2);
#pragma unroll
        for (int j2 = 0; j2 < 8; j2++) {
            uint32_t b[4];
            ldsm_x4_t(b, bk + j2 * 32);
            mma_bf16(acc[2 * j2],     ah[kk], b[0], b[1]);
            mma_bf16(acc[2 * j2 + 1], ah[kk], b[2], b[3]);
            mma_bf16(acc[2 * j2],     al[kk], b[0], b[1]);
            mma_bf16(acc[2 * j2 + 1], al[kk], b[2], b[3]);
        }
    }
}

__device__ __forceinline__ void run_gemm_regA_one(float (&acc)[16][4],
                                                  const uint32_t (&a)[8][4],
                                                  uint32_t bA) {
#pragma unroll
    for (int kk = 0; kk < 8; kk++) {
        uint32_t bk = bA + kk * (16 * PK * 2);
#pragma unroll
        for (int j2 = 0; j2 < 8; j2++) {
            uint32_t b[4];
            ldsm_x4_t(b, bk + j2 * 32);
            mma_bf16(acc[2 * j2],     a[kk], b[0], b[1]);
            mma_bf16(acc[2 * j2 + 1], a[kk], b[2], b[3]);
        }
    }
}

// ---------------------------------------------------------------------------
// Persistent fused kernel.
// ATOMS: D1 = af@W_cf (+b_cf) -> afh (store); msg = b_df*afh;
//        D2 = msg@W_fc; out = af - tanh(D2)
// PAIRS: D1 = dist@W_df (+b_df); msg = D1 * afh[dmj];
//        D2 = msg@W_fc; out[dmi] += tanh(D2)  (run-length-reduced atomics)
// ---------------------------------------------------------------------------
template <bool PAIRS, int K1>
__global__ void __launch_bounds__(256, 1)
dtnn_mma(const float* __restrict__ A,
         const float* __restrict__ W1,      // [K1][128] fp32 (original layout)
         const float* __restrict__ W2,      // [128][128] fp32
         const float* __restrict__ bias1,   // b_cf (atoms) / b_df (pairs)
         const float* __restrict__ bdf,     // b_df (atoms only)
         float* __restrict__ afh,
         const int* __restrict__ dmj,
         const int* __restrict__ dmi,
         float* __restrict__ out,
         int M, int ntiles)
{
    extern __shared__ char sm[];
    const uint32_t smb = smem_to_u32(sm);
    const int tid = threadIdx.x;
    const int lane = tid & 31;
    const int w = tid >> 5;

    float* s_outF = reinterpret_cast<float*>(sm + OFF_AH);
    int* s_dmj = reinterpret_cast<int*>(sm + OFF_IDX);
    int* s_dmi = reinterpret_cast<int*>(sm + OFF_IDX + 512);

    // ---- stage weights (once per CTA), hi/lo split ----
    for (int i = tid; i < 4096; i += 256) {
        const int k = i >> 5;
        const int n4 = (i & 31) << 2;
        float4 v = make_float4(0.f, 0.f, 0.f, 0.f);
        if (k < K1) v = reinterpret_cast<const float4*>(W1)[(k * 128 + n4) >> 2];
        uint32_t h01, l01, h23, l23;
        split_pack(v.x, v.y, h01, l01);
        split_pack(v.z, v.w, h23, l23);
        *reinterpret_cast<uint2*>(sm + OFF_B1H + ((size_t)k * PK + n4) * 2) = make_uint2(h01, h23);
        *reinterpret_cast<uint2*>(sm + OFF_B1L + ((size_t)k * PK + n4) * 2) = make_uint2(l01, l23);

        float4 v2 = reinterpret_cast<const float4*>(W2)[(k * 128 + n4) >> 2];
        split_pack(v2.x, v2.y, h01, l01);
        split_pack(v2.z, v2.w, h23, l23);
        *reinterpret_cast<uint2*>(sm + OFF_B2H + ((size_t)k * PK + n4) * 2) = make_uint2(h01, h23);
        *reinterpret_cast<uint2*>(sm + OFF_B2L + ((size_t)k * PK + n4) * 2) = make_uint2(l01, l23);
    }

    // ---- lane geometry ----
    const int g = lane >> 3, r8 = lane & 7;
    const uint32_t aFragOff = (uint32_t)(((w * 16 + (g & 1) * 8 + r8) * PK + (g >> 1) * 8) * 2);
    const uint32_t bFragOff = (uint32_t)((((g & 1) * 8 + r8) * PK + (g >> 1) * 8) * 2);
    const int rA = w * 16 + (lane >> 2);
    const int rB = rA + 8;
    const int q2 = (lane & 3) * 2;
    constexpr int KS1 = (K1 + 15) / 16;

    const uint32_t uAH = smb + OFF_AH, uAL = smb + OFF_AL;
    const uint32_t uB1H = smb + OFF_B1H, uB1L = smb + OFF_B1L;
    const uint32_t uB2H = smb + OFF_B2H, uB2L = smb + OFF_B2L;

    for (int t = blockIdx.x; t < ntiles; t += gridDim.x) {
        __syncthreads();   // smem reuse guard (covers first-iter weight staging too)
        const int m0 = t << 7;

        // ---- stage A tile (bf16 hi/lo), pad K1..127 with zeros ----
        if (PAIRS) {
            const float* src = A + (size_t)m0 * K1;
            constexpr int NF4 = (128 * K1) / 4;
            for (int i = tid; i < NF4; i += 256) {
                float4 v = reinterpret_cast<const float4*>(src)[i];
                float vv[4] = {v.x, v.y, v.z, v.w};
                const int base = i * 4;
#pragma unroll
                for (int u = 0; u < 4; u++) {
                    const int gi = base + u;
                    const int rr = gi / K1;
                    const int cc = gi - rr * K1;
                    __nv_bfloat16 h = __float2bfloat16(vv[u]);
                    __nv_bfloat16 l = __float2bfloat16(vv[u] - __bfloat162float(h));
                    reinterpret_cast<__nv_bfloat16*>(sm + OFF_AH)[rr * PK + cc] = h;
                    reinterpret_cast<__nv_bfloat16*>(sm + OFF_AL)[rr * PK + cc] = l;
                }
            }
            constexpr int PADN = 128 - K1;
            for (int i = tid; i < 128 * PADN; i += 256) {
                const int rr = i / PADN;
                const int cc = K1 + (i - rr * PADN);
                reinterpret_cast<__nv_bfloat16*>(sm + OFF_AH)[rr * PK + cc] = __float2bfloat16(0.f);
                reinterpret_cast<__nv_bfloat16*>(sm + OFF_AL)[rr * PK + cc] = __float2bfloat16(0.f);
            }
            if (tid < 128) {
                s_dmj[tid] = dmj[m0 + tid];
                s_dmi[tid] = dmi[m0 + tid];
            }
        } else {
            for (int i = tid; i < 4096; i += 256) {
                const int rr = i >> 5;
                const int c4 = (i & 31) << 2;
                float4 v = make_float4(0.f, 0.f, 0.f, 0.f);
                if (m0 + rr < M)
                    v = *reinterpret_cast<const float4*>(A + (size_t)(m0 + rr) * 128 + c4);
                uint32_t h01, l01, h23, l23;
                split_pack(v.x, v.y, h01, l01);
                split_pack(v.z, v.w, h23, l23);
                *reinterpret_cast<uint2*>(sm + OFF_AH + ((size_t)rr * PK + c4) * 2) = make_uint2(h01, h23);
                *reinterpret_cast<uint2*>(sm + OFF_AL + ((size_t)rr * PK + c4) * 2) = make_uint2(l01, l23);
            }
        }
        __syncthreads();

        // ---- GEMM1: Ah@B1h + Al@B1h + Ah@B1l ----
        float acc[16][4];
#pragma unroll
        for (int j = 0; j < 16; j++)
#pragma unroll
            for (int i = 0; i < 4; i++) acc[j][i] = 0.f;

        run_gemm_dual(acc, uAH + aFragOff, uAL + aFragOff, uB1H + bFragOff, KS1);
        run_gemm_one(acc, uAH + aFragOff, uB1L + bFragOff, KS1);

        // ---- Epilogue 1: D1 -> msg fragments (hi/lo), A of GEMM2 ----
        uint32_t a2h[8][4], a2l[8][4];
        int jA = 0, jB = 0;
        if (PAIRS) { jA = s_dmj[rA]; jB = s_dmj[rB]; }
#pragma unroll
        for (int j = 0; j < 16; j++) {
            const int col = j * 8 + q2;
            const float2 b1 = __ldg(reinterpret_cast<const float2*>(bias1 + col));
            float v0 = acc[j][0] + b1.x, v1 = acc[j][1] + b1.y;
            float v2 = acc[j][2] + b1.x, v3 = acc[j][3] + b1.y;
            if (PAIRS) {
                const float2 gA = __ldg(reinterpret_cast<const float2*>(afh + (size_t)jA * 128 + col));
                const float2 gB = __ldg(reinterpret_cast<const float2*>(afh + (size_t)jB * 128 + col));
                v0 *= gA.x; v1 *= gA.y; v2 *= gB.x; v3 *= gB.y;
            } else {
                if (m0 + rA < M)
                    *reinterpret_cast<float2*>(afh + (size_t)(m0 + rA) * 128 + col) = make_float2(v0, v1);
                if (m0 + rB < M)
                    *reinterpret_cast<float2*>(afh + (size_t)(m0 + rB) * 128 + col) = make_float2(v2, v3);
                const float2 bd = __ldg(reinterpret_cast<const float2*>(bdf + col));
                v0 *= bd.x; v1 *= bd.y; v2 *= bd.x; v3 *= bd.y;
            }
            const int kk = j >> 1, h = (j & 1) * 2;
            split_pack(v0, v1, a2h[kk][h], a2l[kk][h]);
            split_pack(v2, v3, a2h[kk][h + 1], a2l[kk][h + 1]);
        }
        __syncthreads();   // all warps done reading A smem before out-tile overlay

        // ---- GEMM2: msgH@B2h + msgL@B2h + msgH@B2l ----
#pragma unroll
        for (int j = 0; j < 16; j++)
#pragma unroll
            for (int i = 0; i < 4; i++) acc[j][i] = 0.f;

        run_gemm_regA_dual(acc, a2h, a2l, uB2H + bFragOff);
        run_gemm_regA_one(acc, a2h, uB2L + bFragOff);

        // ---- Epilogue 2 ----
        if (!PAIRS) {
#pragma unroll
            for (int j = 0; j < 16; j++) {
                const int col = j * 8 + q2;
                if (m0 + rA < M) {
                    const float2 af = __ldg(reinterpret_cast<const float2*>(A + (size_t)(m0 + rA) * 128 + col));
                    *reinterpret_cast<float2*>(out + (size_t)(m0 + rA) * 128 + col) =
                        make_float2(af.x - tanh_fast(acc[j][0]), af.y - tanh_fast(acc[j][1]));
                }
                if (m0 + rB < M) {
                    const float2 af = __ldg(reinterpret_cast<const float2*>(A + (size_t)(m0 + rB) * 128 + col));
                    *reinterpret_cast<float2*>(out + (size_t)(m0 + rB) * 128 + col) =
                        make_float2(af.x - tanh_fast(acc[j][2]), af.y - tanh_fast(acc[j][3]));
                }
            }
        } else {
#pragma unroll
            for (int j = 0; j < 16; j++) {
                const int col = j * 8 + q2;
                *reinterpret_cast<float2*>(s_outF + rA * OUT_STRIDE + col) =
                    make_float2(tanh_fast(acc[j][0]), tanh_fast(acc[j][1]));
                *reinterpret_cast<float2*>(s_outF + rB * OUT_STRIDE + col) =
                    make_float2(tanh_fast(acc[j][2]), tanh_fast(acc[j][3]));
            }
            __syncthreads();
            // run-length segment reduction (dmi is sorted): ~1 atomic per run
            const int c = tid & 127;
            const int r0 = (tid >> 7) << 6;
            float racc = 0.f;
            int cur = s_dmi[r0];
            for (int rr = r0; rr < r0 + 64; rr++) {
                const int ir = s_dmi[rr];
                if (ir != cur) {
                    atomicAdd(out + (size_t)cur * 128 + c, racc);
                    racc = 0.f;
                    cur = ir;
                }
                racc += s_outF[rr * OUT_STRIDE + c];
            }
            atomicAdd(out + (size_t)cur * 128 + c, racc);
        }
    }
}

// ---------------------------------------------------------------------------
extern "C" void kernel_launch(void* const* d_in, const int* in_sizes, int n_in,
                              void* d_out, int out_size)
{
    const float* atom_features = (const float*)d_in[0];
    const float* distance      = (const float*)d_in[1];
    // d_in[2] = atom_membership (unused by the computation)
    const int*   dmi           = (const int*)d_in[3];
    const int*   dmj           = (const int*)d_in[4];
    const float* W_cf          = (const float*)d_in[5];
    const float* W_df          = (const float*)d_in[6];
    const float* W_fc          = (const float*)d_in[7];
    const float* b_cf          = (const float*)d_in[8];
    const float* b_df          = (const float*)d_in[9];
    float* out = (float*)d_out;

    float* afh = nullptr;
    cudaGetSymbolAddress((void**)&afh, g_afh);

    cudaFuncSetAttribute(dtnn_mma<false, 128>,
                         cudaFuncAttributeMaxDynamicSharedMemorySize, SMEM_SZ);
    cudaFuncSetAttribute(dtnn_mma<true, 100>,
                         cudaFuncAttributeMaxDynamicSharedMemorySize, SMEM_SZ);

    const int atom_tiles = (N_ATOMS + 127) / 128;   // 391
    const int pair_tiles = N_PAIRS / 128;           // 6250

    // 1. Atom path: afh + out init (writes every output element)
    dtnn_mma<false, 128><<<152, 256, SMEM_SZ>>>(
        atom_features, W_cf, W_fc, b_cf, b_df, afh, nullptr, nullptr,
        out, N_ATOMS, atom_tiles);

    // 2. Pair path: msgs + run-length-reduced segment sum
    dtnn_mma<true, 100><<<152, 256, SMEM_SZ>>>(
        distance, W_df, W_fc, b_df, nullptr, afh, dmj, dmi,
        out, N_PAIRS, pair_tiles);
}

// round 10
// speedup vs baseline: 3.0584x; 1.1012x over previous
#include <cuda_runtime.h>
#include <cuda_bf16.h>
#include <cstdint>
#include <math.h>

#define N_ATOMS 50000
#define N_PAIRS 800000

// ---------------------------------------------------------------------------
// Device scratch (no cudaMalloc allowed)
// ---------------------------------------------------------------------------
__device__ float g_afh[(size_t)N_ATOMS * 128];   // 25.6 MB, L2-resident

// ---------------------------------------------------------------------------
// SMEM layout (dynamic): bf16 tiles padded to PK=136 cols (272B rows ->
// conflict-free ldmatrix/STS across 8-row strides).
// ---------------------------------------------------------------------------
constexpr int PK = 136;
constexpr int TILE_B = 128 * PK * 2;            // 34816 B per bf16 tile
constexpr int OFF_B1H = 0;
constexpr int OFF_B1L = TILE_B;
constexpr int OFF_B2H = 2 * TILE_B;
constexpr int OFF_B2L = 3 * TILE_B;
constexpr int OFF_AH  = 4 * TILE_B;             // union w/ fp32 out-tile
constexpr int OFF_AL  = OFF_AH + TILE_B;
constexpr int OFF_IDX = OFF_AH + 2 * TILE_B;
constexpr int SMEM_SZ = OFF_IDX + 1024;         // 209920
constexpr int OUT_STRIDE = 132;                 // fp32 out-tile padded stride
constexpr int THREADS = 512;

// ---------------------------------------------------------------------------
// PTX primitives (baseline ISA: sm_80+, compiles for plain sm_103)
// ---------------------------------------------------------------------------
__device__ __forceinline__ uint32_t smem_to_u32(const void* p) {
    uint32_t a;
    asm("{ .reg .u64 t; cvta.to.shared.u64 t, %1; cvt.u32.u64 %0, t; }" : "=r"(a) : "l"(p));
    return a;
}
__device__ __forceinline__ void ldsm_x4(uint32_t (&r)[4], uint32_t addr) {
    asm volatile("ldmatrix.sync.aligned.m8n8.x4.shared.b16 {%0,%1,%2,%3}, [%4];"
                 : "=r"(r[0]), "=r"(r[1]), "=r"(r[2]), "=r"(r[3]) : "r"(addr));
}
__device__ __forceinline__ void ldsm_x4_t(uint32_t (&r)[4], uint32_t addr) {
    asm volatile("ldmatrix.sync.aligned.m8n8.x4.trans.shared.b16 {%0,%1,%2,%3}, [%4];"
                 : "=r"(r[0]), "=r"(r[1]), "=r"(r[2]), "=r"(r[3]) : "r"(addr));
}
__device__ __forceinline__ void mma_bf16(float (&c)[4], const uint32_t (&a)[4],
                                         uint32_t b0, uint32_t b1) {
    asm volatile(
        "mma.sync.aligned.m16n8k16.row.col.f32.bf16.bf16.f32 "
        "{%0,%1,%2,%3}, {%4,%5,%6,%7}, {%8,%9}, {%0,%1,%2,%3};"
        : "+f"(c[0]), "+f"(c[1]), "+f"(c[2]), "+f"(c[3])
        : "r"(a[0]), "r"(a[1]), "r"(a[2]), "r"(a[3]), "r"(b0), "r"(b1));
}

// ---------------------------------------------------------------------------
// Helpers
// ---------------------------------------------------------------------------
__device__ __forceinline__ void split_pack(float a, float b, uint32_t& hi, uint32_t& lo) {
    __nv_bfloat162 h2 = __floats2bfloat162_rn(a, b);
    float2 hf = __bfloat1622float2(h2);
    __nv_bfloat162 l2 = __floats2bfloat162_rn(a - hf.x, b - hf.y);
    hi = *reinterpret_cast<uint32_t*>(&h2);
    lo = *reinterpret_cast<uint32_t*>(&l2);
}
__device__ __forceinline__ float tanh_fast(float x) {
    float e = __expf(2.0f * x);
    return 1.0f - __fdividef(2.0f, e + 1.0f);
}

// ---------------------------------------------------------------------------
// Merged 3-term GEMM: acc += Ah@Bh + Al@Bh + Ah@Bl over ksteps k-chunks of 16.
// Warp tile: 32 rows x 32 cols. acc[mt*4 + j2*2 + h][0..3].
// ---------------------------------------------------------------------------
__device__ __forceinline__ void gemm3(float (&acc)[8][4],
                                      uint32_t aH, uint32_t aL,
                                      uint32_t bH, uint32_t bL, int ksteps) {
    for (int kk = 0; kk < ksteps; kk++) {
        uint32_t ah0[4], ah1[4], al0[4], al1[4];
        ldsm_x4(ah0, aH);
        ldsm_x4(ah1, aH + 16 * PK * 2);
        ldsm_x4(al0, aL);
        ldsm_x4(al1, aL + 16 * PK * 2);
#pragma unroll
        for (int j2 = 0; j2 < 2; j2++) {
            uint32_t b[4];
            ldsm_x4_t(b, bH + j2 * 32);
            mma_bf16(acc[j2 * 2],         ah0, b[0], b[1]);
            mma_bf16(acc[j2 * 2 + 1],     ah0, b[2], b[3]);
            mma_bf16(acc[4 + j2 * 2],     ah1, b[0], b[1]);
            mma_bf16(acc[4 + j2 * 2 + 1], ah1, b[2], b[3]);
            mma_bf16(acc[j2 * 2],         al0, b[0], b[1]);
            mma_bf16(acc[j2 * 2 + 1],     al0, b[2], b[3]);
            mma_bf16(acc[4 + j2 * 2],     al1, b[0], b[1]);
            mma_bf16(acc[4 + j2 * 2 + 1], al1, b[2], b[3]);
            ldsm_x4_t(b, bL + j2 * 32);
            mma_bf16(acc[j2 * 2],         ah0, b[0], b[1]);
            mma_bf16(acc[j2 * 2 + 1],     ah0, b[2], b[3]);
            mma_bf16(acc[4 + j2 * 2],     ah1, b[0], b[1]);
            mma_bf16(acc[4 + j2 * 2 + 1], ah1, b[2], b[3]);
        }
        aH += 32; aL += 32;
        bH += 16 * PK * 2; bL += 16 * PK * 2;
    }
}

// ---------------------------------------------------------------------------
// Persistent fused kernel.
// ATOMS: D1 = af@W_cf (+b_cf) -> afh (store); msg = b_df*afh;
//        D2 = msg@W_fc; out = af - tanh(D2)
// PAIRS: D1 = dist@W_df (+b_df); msg = D1 * afh[dmj];
//        D2 = msg@W_fc; out[dmi] += tanh(D2)  (run-length-reduced atomics)
// msg is exchanged through the (dead) A smem tiles between GEMM1 and GEMM2.
// ---------------------------------------------------------------------------
template <bool PAIRS, int K1>
__global__ void __launch_bounds__(THREADS, 1)
dtnn_mma(const float* __restrict__ A,
         const float* __restrict__ W1,
         const float* __restrict__ W2,
         const float* __restrict__ bias1,
         const float* __restrict__ bdf,
         float* __restrict__ afh,
         const int* __restrict__ dmj,
         const int* __restrict__ dmi,
         float* __restrict__ out,
         int M, int ntiles)
{
    extern __shared__ char sm[];
    const uint32_t smb = smem_to_u32(sm);
    const int tid = threadIdx.x;
    const int lane = tid & 31;
    const int w = tid >> 5;          // 0..15
    const int wm = w & 3;            // row block (32 rows)
    const int wn = w >> 2;           // col block (32 cols)

    float* s_outF = reinterpret_cast<float*>(sm + OFF_AH);
    int* s_dmj = reinterpret_cast<int*>(sm + OFF_IDX);
    int* s_dmi = reinterpret_cast<int*>(sm + OFF_IDX + 512);

    // ---- stage weights once per CTA (hi/lo split, padded rows) ----
    for (int i = tid; i < 4096; i += THREADS) {
        const int k = i >> 5;
        const int n4 = (i & 31) << 2;
        float4 v = make_float4(0.f, 0.f, 0.f, 0.f);
        if (k < K1) v = reinterpret_cast<const float4*>(W1)[(k * 128 + n4) >> 2];
        uint32_t h01, l01, h23, l23;
        split_pack(v.x, v.y, h01, l01);
        split_pack(v.z, v.w, h23, l23);
        *reinterpret_cast<uint2*>(sm + OFF_B1H + ((size_t)k * PK + n4) * 2) = make_uint2(h01, h23);
        *reinterpret_cast<uint2*>(sm + OFF_B1L + ((size_t)k * PK + n4) * 2) = make_uint2(l01, l23);
        float4 v2 = reinterpret_cast<const float4*>(W2)[(k * 128 + n4) >> 2];
        split_pack(v2.x, v2.y, h01, l01);
        split_pack(v2.z, v2.w, h23, l23);
        *reinterpret_cast<uint2*>(sm + OFF_B2H + ((size_t)k * PK + n4) * 2) = make_uint2(h01, h23);
        *reinterpret_cast<uint2*>(sm + OFF_B2L + ((size_t)k * PK + n4) * 2) = make_uint2(l01, l23);
    }

    // ---- lane geometry ----
    const int g = lane >> 3, r8 = lane & 7;
    const uint32_t aOff =
        (uint32_t)(((wm * 32 + (g & 1) * 8 + r8) * PK + (g >> 1) * 8) * 2);
    const uint32_t bOff =
        (uint32_t)((((g & 1) * 8 + r8) * PK + (g >> 1) * 8) * 2) + (uint32_t)wn * 64;
    const int rBase = wm * 32 + (lane >> 2);      // epilogue row base
    const int q2 = (lane & 3) * 2;
    const int cBase = wn * 32;
    constexpr int KS1 = (K1 + 15) / 16;

    const uint32_t uAH = smb + OFF_AH, uAL = smb + OFF_AL;
    const uint32_t uB1H = smb + OFF_B1H, uB1L = smb + OFF_B1L;
    const uint32_t uB2H = smb + OFF_B2H, uB2L = smb + OFF_B2L;

    for (int t = blockIdx.x; t < ntiles; t += gridDim.x) {
        __syncthreads();   // smem reuse guard (also covers weight staging, iter 0)
        const int m0 = t << 7;

        // ---- stage A tile (bf16 hi/lo) ----
        if (PAIRS) {
            const float* src = A + (size_t)m0 * K1;
            // K1=100: thread i handles float4 #i -> row i/25, cols (i%25)*4
            for (int i = tid; i < 128 * (K1 / 4); i += THREADS) {
                const int rr = i / (K1 / 4);
                const int c0 = (i - rr * (K1 / 4)) * 4;
                float4 v = reinterpret_cast<const float4*>(src)[i];
                uint32_t h01, l01, h23, l23;
                split_pack(v.x, v.y, h01, l01);
                split_pack(v.z, v.w, h23, l23);
                *reinterpret_cast<uint2*>(sm + OFF_AH + ((size_t)rr * PK + c0) * 2) = make_uint2(h01, h23);
                *reinterpret_cast<uint2*>(sm + OFF_AL + ((size_t)rr * PK + c0) * 2) = make_uint2(l01, l23);
            }
            // zero-pad cols K1..KS1*16
            constexpr int PADN = KS1 * 16 - K1;
            for (int i = tid; i < 128 * PADN; i += THREADS) {
                const int rr = i / PADN;
                const int cc = K1 + (i - rr * PADN);
                reinterpret_cast<__nv_bfloat16*>(sm + OFF_AH)[rr * PK + cc] = __float2bfloat16(0.f);
                reinterpret_cast<__nv_bfloat16*>(sm + OFF_AL)[rr * PK + cc] = __float2bfloat16(0.f);
            }
            if (tid < 128) {
                s_dmj[tid] = dmj[m0 + tid];
                s_dmi[tid] = dmi[m0 + tid];
            }
        } else {
            for (int i = tid; i < 4096; i += THREADS) {
                const int rr = i >> 5;
                const int c4 = (i & 31) << 2;
                float4 v = make_float4(0.f, 0.f, 0.f, 0.f);
                if (m0 + rr < M)
                    v = *reinterpret_cast<const float4*>(A + (size_t)(m0 + rr) * 128 + c4);
                uint32_t h01, l01, h23, l23;
                split_pack(v.x, v.y, h01, l01);
                split_pack(v.z, v.w, h23, l23);
                *reinterpret_cast<uint2*>(sm + OFF_AH + ((size_t)rr * PK + c4) * 2) = make_uint2(h01, h23);
                *reinterpret_cast<uint2*>(sm + OFF_AL + ((size_t)rr * PK + c4) * 2) = make_uint2(l01, l23);
            }
        }
        __syncthreads();

        // ---- GEMM1 ----
        float acc[8][4];
#pragma unroll
        for (int j = 0; j < 8; j++)
#pragma unroll
            for (int i = 0; i < 4; i++) acc[j][i] = 0.f;
        gemm3(acc, uAH + aOff, uAL + aOff, uB1H + bOff, uB1L + bOff, KS1);

        // ---- Epilogue 1 (compute msg in-place in acc) ----
        int jrow[4];
        if (PAIRS) {
#pragma unroll
            for (int s = 0; s < 4; s++) jrow[s] = s_dmj[rBase + s * 8];
        }
#pragma unroll
        for (int mt = 0; mt < 2; mt++) {
#pragma unroll
            for (int jh = 0; jh < 4; jh++) {           // jh = j2*2 + h
                const int ai = mt * 4 + jh;
                const int col = cBase + jh * 8 + q2;
                const float2 b1 = __ldg(reinterpret_cast<const float2*>(bias1 + col));
                float v0 = acc[ai][0] + b1.x, v1 = acc[ai][1] + b1.y;
                float v2 = acc[ai][2] + b1.x, v3 = acc[ai][3] + b1.y;
                if (PAIRS) {
                    const float2 gA = __ldg(reinterpret_cast<const float2*>(
                        afh + (size_t)jrow[mt * 2] * 128 + col));
                    const float2 gB = __ldg(reinterpret_cast<const float2*>(
                        afh + (size_t)jrow[mt * 2 + 1] * 128 + col));
                    v0 *= gA.x; v1 *= gA.y; v2 *= gB.x; v3 *= gB.y;
                } else {
                    const int rA = m0 + rBase + mt * 16;
                    if (rA < M)
                        *reinterpret_cast<float2*>(afh + (size_t)rA * 128 + col) = make_float2(v0, v1);
                    if (rA + 8 < M)
                        *reinterpret_cast<float2*>(afh + (size_t)(rA + 8) * 128 + col) = make_float2(v2, v3);
                    const float2 bd = __ldg(reinterpret_cast<const float2*>(bdf + col));
                    v0 *= bd.x; v1 *= bd.y; v2 *= bd.x; v3 *= bd.y;
                }
                acc[ai][0] = v0; acc[ai][1] = v1; acc[ai][2] = v2; acc[ai][3] = v3;
            }
        }
        __syncthreads();   // all warps done reading A tiles

        // ---- exchange msg through A smem (hi/lo) ----
#pragma unroll
        for (int mt = 0; mt < 2; mt++) {
            const int r0 = rBase + mt * 16;
#pragma unroll
            for (int jh = 0; jh < 4; jh++) {
                const int ai = mt * 4 + jh;
                const int col = cBase + jh * 8 + q2;
                uint32_t hi, lo;
                split_pack(acc[ai][0], acc[ai][1], hi, lo);
                *reinterpret_cast<uint32_t*>(sm + OFF_AH + ((size_t)r0 * PK + col) * 2) = hi;
                *reinterpret_cast<uint32_t*>(sm + OFF_AL + ((size_t)r0 * PK + col) * 2) = lo;
                split_pack(acc[ai][2], acc[ai][3], hi, lo);
                *reinterpret_cast<uint32_t*>(sm + OFF_AH + ((size_t)(r0 + 8) * PK + col) * 2) = hi;
                *reinterpret_cast<uint32_t*>(sm + OFF_AL + ((size_t)(r0 + 8) * PK + col) * 2) = lo;
            }
        }
        __syncthreads();

        // ---- GEMM2 ----
#pragma unroll
        for (int j = 0; j < 8; j++)
#pragma unroll
            for (int i = 0; i < 4; i++) acc[j][i] = 0.f;
        gemm3(acc, uAH + aOff, uAL + aOff, uB2H + bOff, uB2L + bOff, 8);

        // ---- Epilogue 2 ----
        if (!PAIRS) {
#pragma unroll
            for (int mt = 0; mt < 2; mt++) {
#pragma unroll
                for (int jh = 0; jh < 4; jh++) {
                    const int ai = mt * 4 + jh;
                    const int col = cBase + jh * 8 + q2;
                    const int rA = m0 + rBase + mt * 16;
                    if (rA < M) {
                        const float2 af = __ldg(reinterpret_cast<const float2*>(
                            A + (size_t)rA * 128 + col));
                        *reinterpret_cast<float2*>(out + (size_t)rA * 128 + col) =
                            make_float2(af.x - tanh_fast(acc[ai][0]),
                                        af.y - tanh_fast(acc[ai][1]));
                    }
                    if (rA + 8 < M) {
                        const float2 af = __ldg(reinterpret_cast<const float2*>(
                            A + (size_t)(rA + 8) * 128 + col));
                        *reinterpret_cast<float2*>(out + (size_t)(rA + 8) * 128 + col) =
                            make_float2(af.x - tanh_fast(acc[ai][2]),
                                        af.y - tanh_fast(acc[ai][3]));
                    }
                }
            }
        } else {
            __syncthreads();   // all warps done reading msg tiles before overlay
#pragma unroll
            for (int mt = 0; mt < 2; mt++) {
                const int r0 = rBase + mt * 16;
#pragma unroll
                for (int jh = 0; jh < 4; jh++) {
                    const int ai = mt * 4 + jh;
                    const int col = cBase + jh * 8 + q2;
                    *reinterpret_cast<float2*>(s_outF + r0 * OUT_STRIDE + col) =
                        make_float2(tanh_fast(acc[ai][0]), tanh_fast(acc[ai][1]));
                    *reinterpret_cast<float2*>(s_outF + (r0 + 8) * OUT_STRIDE + col) =
                        make_float2(tanh_fast(acc[ai][2]), tanh_fast(acc[ai][3]));
                }
            }
            __syncthreads();
            // run-length segment reduction (dmi is sorted): ~1 atomic per run
            const int c = tid & 127;
            const int r0 = (tid >> 7) << 5;   // 4 segments x 32 rows
            float racc = 0.f;
            int cur = s_dmi[r0];
            for (int rr = r0; rr < r0 + 32; rr++) {
                const int ir = s_dmi[rr];
                if (ir != cur) {
                    atomicAdd(out + (size_t)cur * 128 + c, racc);
                    racc = 0.f;
                    cur = ir;
                }
                racc += s_outF[rr * OUT_STRIDE + c];
            }
            atomicAdd(out + (size_t)cur * 128 + c, racc);
        }
    }
}

// ---------------------------------------------------------------------------
extern "C" void kernel_launch(void* const* d_in, const int* in_sizes, int n_in,
                              void* d_out, int out_size)
{
    const float* atom_features = (const float*)d_in[0];
    const float* distance      = (const float*)d_in[1];
    // d_in[2] = atom_membership (unused by the computation)
    const int*   dmi           = (const int*)d_in[3];
    const int*   dmj           = (const int*)d_in[4];
    const float* W_cf          = (const float*)d_in[5];
    const float* W_df          = (const float*)d_in[6];
    const float* W_fc          = (const float*)d_in[7];
    const float* b_cf          = (const float*)d_in[8];
    const float* b_df          = (const float*)d_in[9];
    float* out = (float*)d_out;

    float* afh = nullptr;
    cudaGetSymbolAddress((void**)&afh, g_afh);

    cudaFuncSetAttribute(dtnn_mma<false, 128>,
                         cudaFuncAttributeMaxDynamicSharedMemorySize, SMEM_SZ);
    cudaFuncSetAttribute(dtnn_mma<true, 100>,
                         cudaFuncAttributeMaxDynamicSharedMemorySize, SMEM_SZ);

    const int atom_tiles = (N_ATOMS + 127) / 128;   // 391
    const int pair_tiles = N_PAIRS / 128;           // 6250

    // 1. Atom path: afh + out init (writes every output element)
    dtnn_mma<false, 128><<<152, THREADS, SMEM_SZ>>>(
        atom_features, W_cf, W_fc, b_cf, b_df, afh, nullptr, nullptr,
        out, N_ATOMS, atom_tiles);

    // 2. Pair path: msgs + run-length-reduced segment sum
    dtnn_mma<true, 100><<<152, THREADS, SMEM_SZ>>>(
        distance, W_df, W_fc, b_df, nullptr, afh, dmj, dmi,
        out, N_PAIRS, pair_tiles);
}

// round 12
// speedup vs baseline: 3.0687x; 1.0034x over previous
#include <cuda_runtime.h>
#include <cuda_bf16.h>
#include <cstdint>
#include <math.h>

#define N_ATOMS 50000
#define N_PAIRS 800000

// ---------------------------------------------------------------------------
// Device scratch (no cudaMalloc allowed)
// ---------------------------------------------------------------------------
__device__ float g_afh[(size_t)N_ATOMS * 128];   // 25.6 MB, L2-resident

// ---------------------------------------------------------------------------
// SMEM layout (dynamic): bf16 tiles padded to PK=136 cols (272B rows ->
// conflict-free ldmatrix/STS across 8-row strides).
// ---------------------------------------------------------------------------
constexpr int PK = 136;
constexpr int TILE_B = 128 * PK * 2;            // 34816 B per bf16 tile
constexpr int OFF_B1H = 0;
constexpr int OFF_B1L = TILE_B;
constexpr int OFF_B2H = 2 * TILE_B;
constexpr int OFF_B2L = 3 * TILE_B;
constexpr int OFF_AH  = 4 * TILE_B;             // union w/ fp32 out-tile
constexpr int OFF_AL  = OFF_AH + TILE_B;
constexpr int OFF_IDX = OFF_AH + 2 * TILE_B;
constexpr int SMEM_SZ = OFF_IDX + 1024;         // 209920
constexpr int OUT_STRIDE = 132;                 // fp32 out-tile padded stride
constexpr int THREADS = 512;

// ---------------------------------------------------------------------------
// PTX primitives (baseline ISA: sm_80+, compiles for plain sm_103)
// ---------------------------------------------------------------------------
__device__ __forceinline__ uint32_t smem_to_u32(const void* p) {
    uint32_t a;
    asm("{ .reg .u64 t; cvta.to.shared.u64 t, %1; cvt.u32.u64 %0, t; }" : "=r"(a) : "l"(p));
    return a;
}
__device__ __forceinline__ void ldsm_x4(uint32_t (&r)[4], uint32_t addr) {
    asm volatile("ldmatrix.sync.aligned.m8n8.x4.shared.b16 {%0,%1,%2,%3}, [%4];"
                 : "=r"(r[0]), "=r"(r[1]), "=r"(r[2]), "=r"(r[3]) : "r"(addr));
}
__device__ __forceinline__ void ldsm_x4_t(uint32_t (&r)[4], uint32_t addr) {
    asm volatile("ldmatrix.sync.aligned.m8n8.x4.trans.shared.b16 {%0,%1,%2,%3}, [%4];"
                 : "=r"(r[0]), "=r"(r[1]), "=r"(r[2]), "=r"(r[3]) : "r"(addr));
}
__device__ __forceinline__ void mma_bf16(float (&c)[4], const uint32_t (&a)[4],
                                         uint32_t b0, uint32_t b1) {
    asm volatile(
        "mma.sync.aligned.m16n8k16.row.col.f32.bf16.bf16.f32 "
        "{%0,%1,%2,%3}, {%4,%5,%6,%7}, {%8,%9}, {%0,%1,%2,%3};"
        : "+f"(c[0]), "+f"(c[1]), "+f"(c[2]), "+f"(c[3])
        : "r"(a[0]), "r"(a[1]), "r"(a[2]), "r"(a[3]), "r"(b0), "r"(b1));
}

// ---------------------------------------------------------------------------
// Helpers
// ---------------------------------------------------------------------------
__device__ __forceinline__ void split_pack(float a, float b, uint32_t& hi, uint32_t& lo) {
    __nv_bfloat162 h2 = __floats2bfloat162_rn(a, b);
    float2 hf = __bfloat1622float2(h2);
    __nv_bfloat162 l2 = __floats2bfloat162_rn(a - hf.x, b - hf.y);
    hi = *reinterpret_cast<uint32_t*>(&h2);
    lo = *reinterpret_cast<uint32_t*>(&l2);
}
__device__ __forceinline__ float tanh_fast(float x) {
    float e = __expf(2.0f * x);
    return 1.0f - __fdividef(2.0f, e + 1.0f);
}

// ---------------------------------------------------------------------------
// Merged 3-term GEMM: acc += Ah@Bh + Al@Bh + Ah@Bl over ksteps k-chunks of 16.
// Warp tile 32x32. Per k-step: batch ALL 8 ldsm up front, then 24 MMAs
// round-robin across all 8 accumulators (revisit spacing 8 >= HMMA latency).
// acc[mt*4 + j2*2 + h].
// ---------------------------------------------------------------------------
__device__ __forceinline__ void gemm3(float (&acc)[8][4],
                                      uint32_t aH, uint32_t aL,
                                      uint32_t bH, uint32_t bL, int ksteps) {
    for (int kk = 0; kk < ksteps; kk++) {
        uint32_t ah0[4], ah1[4], al0[4], al1[4];
        uint32_t b0[4], b1[4], c0[4], c1[4];
        // issue-ordered: first-needed fragments first
        ldsm_x4(ah0, aH);
        ldsm_x4_t(b0, bH);
        ldsm_x4(ah1, aH + 16 * PK * 2);
        ldsm_x4_t(b1, bH + 32);
        ldsm_x4(al0, aL);
        ldsm_x4(al1, aL + 16 * PK * 2);
        ldsm_x4_t(c0, bL);
        ldsm_x4_t(c1, bL + 32);
        // round 1: Ah x Bh
        mma_bf16(acc[0], ah0, b0[0], b0[1]);
        mma_bf16(acc[1], ah0, b0[2], b0[3]);
        mma_bf16(acc[4], ah1, b0[0], b0[1]);
        mma_bf16(acc[5], ah1, b0[2], b0[3]);
        mma_bf16(acc[2], ah0, b1[0], b1[1]);
        mma_bf16(acc[3], ah0, b1[2], b1[3]);
        mma_bf16(acc[6], ah1, b1[0], b1[1]);
        mma_bf16(acc[7], ah1, b1[2], b1[3]);
        // round 2: Al x Bh
        mma_bf16(acc[0], al0, b0[0], b0[1]);
        mma_bf16(acc[1], al0, b0[2], b0[3]);
        mma_bf16(acc[4], al1, b0[0], b0[1]);
        mma_bf16(acc[5], al1, b0[2], b0[3]);
        mma_bf16(acc[2], al0, b1[0], b1[1]);
        mma_bf16(acc[3], al0, b1[2], b1[3]);
        mma_bf16(acc[6], al1, b1[0], b1[1]);
        mma_bf16(acc[7], al1, b1[2], b1[3]);
        // round 3: Ah x Bl
        mma_bf16(acc[0], ah0, c0[0], c0[1]);
        mma_bf16(acc[1], ah0, c0[2], c0[3]);
        mma_bf16(acc[4], ah1, c0[0], c0[1]);
        mma_bf16(acc[5], ah1, c0[2], c0[3]);
        mma_bf16(acc[2], ah0, c1[0], c1[1]);
        mma_bf16(acc[3], ah0, c1[2], c1[3]);
        mma_bf16(acc[6], ah1, c1[0], c1[1]);
        mma_bf16(acc[7], ah1, c1[2], c1[3]);

        aH += 32; aL += 32;
        bH += 16 * PK * 2; bL += 16 * PK * 2;
    }
}

// ---------------------------------------------------------------------------
// Persistent fused kernel.
// ATOMS: D1 = af@W_cf (+b_cf) -> afh (store); msg = b_df*afh;
//        D2 = msg@W_fc; out = af - tanh(D2)
// PAIRS: D1 = dist@W_df (+b_df); msg = D1 * afh[dmj];
//        D2 = msg@W_fc; out[dmi] += tanh(D2)  (run-length-reduced atomics)
// msg is exchanged through the (dead) A smem tiles between GEMM1 and GEMM2.
// ---------------------------------------------------------------------------
template <bool PAIRS, int K1>
__global__ void __launch_bounds__(THREADS, 1)
dtnn_mma(const float* __restrict__ A,
         const float* __restrict__ W1,
         const float* __restrict__ W2,
         const float* __restrict__ bias1,
         const float* __restrict__ bdf,
         float* __restrict__ afh,
         const int* __restrict__ dmj,
         const int* __restrict__ dmi,
         float* __restrict__ out,
         int M, int ntiles)
{
    extern __shared__ char sm[];
    const uint32_t smb = smem_to_u32(sm);
    const int tid = threadIdx.x;
    const int lane = tid & 31;
    const int w = tid >> 5;          // 0..15
    const int wm = w & 3;            // row block (32 rows)
    const int wn = w >> 2;           // col block (32 cols)

    float* s_outF = reinterpret_cast<float*>(sm + OFF_AH);
    int* s_dmj = reinterpret_cast<int*>(sm + OFF_IDX);
    int* s_dmi = reinterpret_cast<int*>(sm + OFF_IDX + 512);

    // ---- stage weights once per CTA (hi/lo split, padded rows) ----
    for (int i = tid; i < 4096; i += THREADS) {
        const int k = i >> 5;
        const int n4 = (i & 31) << 2;
        float4 v = make_float4(0.f, 0.f, 0.f, 0.f);
        if (k < K1) v = reinterpret_cast<const float4*>(W1)[(k * 128 + n4) >> 2];
        uint32_t h01, l01, h23, l23;
        split_pack(v.x, v.y, h01, l01);
        split_pack(v.z, v.w, h23, l23);
        *reinterpret_cast<uint2*>(sm + OFF_B1H + ((size_t)k * PK + n4) * 2) = make_uint2(h01, h23);
        *reinterpret_cast<uint2*>(sm + OFF_B1L + ((size_t)k * PK + n4) * 2) = make_uint2(l01, l23);
        float4 v2 = reinterpret_cast<const float4*>(W2)[(k * 128 + n4) >> 2];
        split_pack(v2.x, v2.y, h01, l01);
        split_pack(v2.z, v2.w, h23, l23);
        *reinterpret_cast<uint2*>(sm + OFF_B2H + ((size_t)k * PK + n4) * 2) = make_uint2(h01, h23);
        *reinterpret_cast<uint2*>(sm + OFF_B2L + ((size_t)k * PK + n4) * 2) = make_uint2(l01, l23);
    }

    // ---- lane geometry ----
    const int g = lane >> 3, r8 = lane & 7;
    const uint32_t aOff =
        (uint32_t)(((wm * 32 + (g & 1) * 8 + r8) * PK + (g >> 1) * 8) * 2);
    const uint32_t bOff =
        (uint32_t)((((g & 1) * 8 + r8) * PK + (g >> 1) * 8) * 2) + (uint32_t)wn * 64;
    const int rBase = wm * 32 + (lane >> 2);      // epilogue row base
    const int q2 = (lane & 3) * 2;
    const int cBase = wn * 32;
    constexpr int KS1 = (K1 + 15) / 16;

    const uint32_t uAH = smb + OFF_AH, uAL = smb + OFF_AL;
    const uint32_t uB1H = smb + OFF_B1H, uB1L = smb + OFF_B1L;
    const uint32_t uB2H = smb + OFF_B2H, uB2L = smb + OFF_B2L;

    for (int t = blockIdx.x; t < ntiles; t += gridDim.x) {
        __syncthreads();   // smem reuse guard (also covers weight staging, iter 0)
        const int m0 = t << 7;

        // ---- stage A tile (bf16 hi/lo) ----
        if (PAIRS) {
            const float* src = A + (size_t)m0 * K1;
            for (int i = tid; i < 128 * (K1 / 4); i += THREADS) {
                const int rr = i / (K1 / 4);
                const int c0 = (i - rr * (K1 / 4)) * 4;
                float4 v = reinterpret_cast<const float4*>(src)[i];
                uint32_t h01, l01, h23, l23;
                split_pack(v.x, v.y, h01, l01);
                split_pack(v.z, v.w, h23, l23);
                *reinterpret_cast<uint2*>(sm + OFF_AH + ((size_t)rr * PK + c0) * 2) = make_uint2(h01, h23);
                *reinterpret_cast<uint2*>(sm + OFF_AL + ((size_t)rr * PK + c0) * 2) = make_uint2(l01, l23);
            }
            constexpr int PADN = KS1 * 16 - K1;
            for (int i = tid; i < 128 * PADN; i += THREADS) {
                const int rr = i / PADN;
                const int cc = K1 + (i - rr * PADN);
                reinterpret_cast<__nv_bfloat16*>(sm + OFF_AH)[rr * PK + cc] = __float2bfloat16(0.f);
                reinterpret_cast<__nv_bfloat16*>(sm + OFF_AL)[rr * PK + cc] = __float2bfloat16(0.f);
            }
            if (tid < 128) {
                s_dmj[tid] = dmj[m0 + tid];
                s_dmi[tid] = dmi[m0 + tid];
            }
        } else {
            for (int i = tid; i < 4096; i += THREADS) {
                const int rr = i >> 5;
                const int c4 = (i & 31) << 2;
                float4 v = make_float4(0.f, 0.f, 0.f, 0.f);
                if (m0 + rr < M)
                    v = *reinterpret_cast<const float4*>(A + (size_t)(m0 + rr) * 128 + c4);
                uint32_t h01, l01, h23, l23;
                split_pack(v.x, v.y, h01, l01);
                split_pack(v.z, v.w, h23, l23);
                *reinterpret_cast<uint2*>(sm + OFF_AH + ((size_t)rr * PK + c4) * 2) = make_uint2(h01, h23);
                *reinterpret_cast<uint2*>(sm + OFF_AL + ((size_t)rr * PK + c4) * 2) = make_uint2(l01, l23);
            }
        }
        __syncthreads();

        // hoist gather indices (hides LDS latency under GEMM1)
        int jrow[4];
        if (PAIRS) {
#pragma unroll
            for (int s = 0; s < 4; s++) jrow[s] = s_dmj[rBase + s * 8];
        }

        // ---- GEMM1 ----
        float acc[8][4];
#pragma unroll
        for (int j = 0; j < 8; j++)
#pragma unroll
            for (int i = 0; i < 4; i++) acc[j][i] = 0.f;
        gemm3(acc, uAH + aOff, uAL + aOff, uB1H + bOff, uB1L + bOff, KS1);

        // ---- Epilogue 1 (compute msg in-place in acc) ----
#pragma unroll
        for (int mt = 0; mt < 2; mt++) {
#pragma unroll
            for (int jh = 0; jh < 4; jh++) {
                const int ai = mt * 4 + jh;
                const int col = cBase + jh * 8 + q2;
                const float2 b1 = __ldg(reinterpret_cast<const float2*>(bias1 + col));
                float v0 = acc[ai][0] + b1.x, v1 = acc[ai][1] + b1.y;
                float v2 = acc[ai][2] + b1.x, v3 = acc[ai][3] + b1.y;
                if (PAIRS) {
                    const float2 gA = __ldg(reinterpret_cast<const float2*>(
                        afh + (size_t)jrow[mt * 2] * 128 + col));
                    const float2 gB = __ldg(reinterpret_cast<const float2*>(
                        afh + (size_t)jrow[mt * 2 + 1] * 128 + col));
                    v0 *= gA.x; v1 *= gA.y; v2 *= gB.x; v3 *= gB.y;
                } else {
                    const int rA = m0 + rBase + mt * 16;
                    if (rA < M)
                        *reinterpret_cast<float2*>(afh + (size_t)rA * 128 + col) = make_float2(v0, v1);
                    if (rA + 8 < M)
                        *reinterpret_cast<float2*>(afh + (size_t)(rA + 8) * 128 + col) = make_float2(v2, v3);
                    const float2 bd = __ldg(reinterpret_cast<const float2*>(bdf + col));
                    v0 *= bd.x; v1 *= bd.y; v2 *= bd.x; v3 *= bd.y;
                }
                acc[ai][0] = v0; acc[ai][1] = v1; acc[ai][2] = v2; acc[ai][3] = v3;
            }
        }
        __syncthreads();   // all warps done reading A tiles

        // ---- exchange msg through A smem (hi/lo) ----
#pragma unroll
        for (int mt = 0; mt < 2; mt++) {
            const int r0 = rBase + mt * 16;
#pragma unroll
            for (int jh = 0; jh < 4; jh++) {
                const int ai = mt * 4 + jh;
                const int col = cBase + jh * 8 + q2;
                uint32_t hi, lo;
                split_pack(acc[ai][0], acc[ai][1], hi, lo);
                *reinterpret_cast<uint32_t*>(sm + OFF_AH + ((size_t)r0 * PK + col) * 2) = hi;
                *reinterpret_cast<uint32_t*>(sm + OFF_AL + ((size_t)r0 * PK + col) * 2) = lo;
                split_pack(acc[ai][2], acc[ai][3], hi, lo);
                *reinterpret_cast<uint32_t*>(sm + OFF_AH + ((size_t)(r0 + 8) * PK + col) * 2) = hi;
                *reinterpret_cast<uint32_t*>(sm + OFF_AL + ((size_t)(r0 + 8) * PK + col) * 2) = lo;
            }
        }
        __syncthreads();

        // ---- GEMM2 ----
#pragma unroll
        for (int j = 0; j < 8; j++)
#pragma unroll
            for (int i = 0; i < 4; i++) acc[j][i] = 0.f;
        gemm3(acc, uAH + aOff, uAL + aOff, uB2H + bOff, uB2L + bOff, 8);

        // ---- Epilogue 2 ----
        if (!PAIRS) {
#pragma unroll
            for (int mt = 0; mt < 2; mt++) {
#pragma unroll
                for (int jh = 0; jh < 4; jh++) {
                    const int ai = mt * 4 + jh;
                    const int col = cBase + jh * 8 + q2;
                    const int rA = m0 + rBase + mt * 16;
                    if (rA < M) {
                        const float2 af = __ldg(reinterpret_cast<const float2*>(
                            A + (size_t)rA * 128 + col));
                        *reinterpret_cast<float2*>(out + (size_t)rA * 128 + col) =
                            make_float2(af.x - tanh_fast(acc[ai][0]),
                                        af.y - tanh_fast(acc[ai][1]));
                    }
                    if (rA + 8 < M) {
                        const float2 af = __ldg(reinterpret_cast<const float2*>(
                            A + (size_t)(rA + 8) * 128 + col));
                        *reinterpret_cast<float2*>(out + (size_t)(rA + 8) * 128 + col) =
                            make_float2(af.x - tanh_fast(acc[ai][2]),
                                        af.y - tanh_fast(acc[ai][3]));
                    }
                }
            }
        } else {
            __syncthreads();   // all warps done reading msg tiles before overlay
#pragma unroll
            for (int mt = 0; mt < 2; mt++) {
                const int r0 = rBase + mt * 16;
#pragma unroll
                for (int jh = 0; jh < 4; jh++) {
                    const int ai = mt * 4 + jh;
                    const int col = cBase + jh * 8 + q2;
                    *reinterpret_cast<float2*>(s_outF + r0 * OUT_STRIDE + col) =
                        make_float2(tanh_fast(acc[ai][0]), tanh_fast(acc[ai][1]));
                    *reinterpret_cast<float2*>(s_outF + (r0 + 8) * OUT_STRIDE + col) =
                        make_float2(tanh_fast(acc[ai][2]), tanh_fast(acc[ai][3]));
                }
            }
            __syncthreads();
            // run-length segment reduction (dmi is sorted): ~1 atomic per run
            const int c = tid & 127;
            const int r0 = (tid >> 7) << 5;   // 4 segments x 32 rows
            float racc = 0.f;
            int cur = s_dmi[r0];
            for (int rr = r0; rr < r0 + 32; rr++) {
                const int ir = s_dmi[rr];
                if (ir != cur) {
                    atomicAdd(out + (size_t)cur * 128 + c, racc);
                    racc = 0.f;
                    cur = ir;
                }
                racc += s_outF[rr * OUT_STRIDE + c];
            }
            atomicAdd(out + (size_t)cur * 128 + c, racc);
        }
    }
}

// ---------------------------------------------------------------------------
extern "C" void kernel_launch(void* const* d_in, const int* in_sizes, int n_in,
                              void* d_out, int out_size)
{
    const float* atom_features = (const float*)d_in[0];
    const float* distance      = (const float*)d_in[1];
    // d_in[2] = atom_membership (unused by the computation)
    const int*   dmi           = (const int*)d_in[3];
    const int*   dmj           = (const int*)d_in[4];
    const float* W_cf          = (const float*)d_in[5];
    const float* W_df          = (const float*)d_in[6];
    const float* W_fc          = (const float*)d_in[7];
    const float* b_cf          = (const float*)d_in[8];
    const float* b_df          = (const float*)d_in[9];
    float* out = (float*)d_out;

    float* afh = nullptr;
    cudaGetSymbolAddress((void**)&afh, g_afh);

    cudaFuncSetAttribute(dtnn_mma<false, 128>,
                         cudaFuncAttributeMaxDynamicSharedMemorySize, SMEM_SZ);
    cudaFuncSetAttribute(dtnn_mma<true, 100>,
                         cudaFuncAttributeMaxDynamicSharedMemorySize, SMEM_SZ);

    const int atom_tiles = (N_ATOMS + 127) / 128;   // 391
    const int pair_tiles = N_PAIRS / 128;           // 6250

    // 1. Atom path: afh + out init (writes every output element)
    dtnn_mma<false, 128><<<152, THREADS, SMEM_SZ>>>(
        atom_features, W_cf, W_fc, b_cf, b_df, afh, nullptr, nullptr,
        out, N_ATOMS, atom_tiles);

    // 2. Pair path: msgs + run-length-reduced segment sum
    dtnn_mma<true, 100><<<152, THREADS, SMEM_SZ>>>(
        distance, W_df, W_fc, b_df, nullptr, afh, dmj, dmi,
        out, N_PAIRS, pair_tiles);
}

// round 15
// speedup vs baseline: 3.0888x; 1.0065x over previous
#include <cuda_runtime.h>
#include <cuda_bf16.h>
#include <cstdint>
#include <math.h>

#define N_ATOMS 50000
#define N_PAIRS 800000

// ---------------------------------------------------------------------------
// Device scratch (no cudaMalloc allowed)
// ---------------------------------------------------------------------------
__device__ float g_afh[(size_t)N_ATOMS * 128];   // 25.6 MB, L2-resident

// ---------------------------------------------------------------------------
// SMEM layout (dynamic): bf16 tiles padded to PK=136 cols (272B rows ->
// conflict-free ldmatrix/STS across 8-row strides).
// B tiles (shared, read-only after staging): B1H B1L B2H B2L.
// A region: per-half blocks. Half h owns [OFF_A + h*TILE_B, +TILE_B):
//   hi rows 0..63 at +0, lo rows 0..63 at +TILE_B/2.
//   (fp32 out-tile overlay for the pairs epilogue also fits in this block.)
// ---------------------------------------------------------------------------
constexpr int PK = 136;
constexpr int TILE_B = 128 * PK * 2;            // 34816 B
constexpr int OFF_B1H = 0;
constexpr int OFF_B1L = TILE_B;
constexpr int OFF_B2H = 2 * TILE_B;
constexpr int OFF_B2L = 3 * TILE_B;
constexpr int OFF_A   = 4 * TILE_B;             // two per-half blocks
constexpr int OFF_IDX = OFF_A + 2 * TILE_B;
constexpr int SMEM_SZ = OFF_IDX + 1024;         // 209920
constexpr int OUT_STRIDE = 132;                 // fp32 out-tile padded stride
constexpr int THREADS = 512;

// ---------------------------------------------------------------------------
// PTX primitives (baseline ISA: sm_80+, compiles for plain sm_103)
// ---------------------------------------------------------------------------
__device__ __forceinline__ uint32_t smem_to_u32(const void* p) {
    uint32_t a;
    asm("{ .reg .u64 t; cvta.to.shared.u64 t, %1; cvt.u32.u64 %0, t; }" : "=r"(a) : "l"(p));
    return a;
}
__device__ __forceinline__ void ldsm_x4(uint32_t (&r)[4], uint32_t addr) {
    asm volatile("ldmatrix.sync.aligned.m8n8.x4.shared.b16 {%0,%1,%2,%3}, [%4];"
                 : "=r"(r[0]), "=r"(r[1]), "=r"(r[2]), "=r"(r[3]) : "r"(addr));
}
__device__ __forceinline__ void ldsm_x4_t(uint32_t (&r)[4], uint32_t addr) {
    asm volatile("ldmatrix.sync.aligned.m8n8.x4.trans.shared.b16 {%0,%1,%2,%3}, [%4];"
                 : "=r"(r[0]), "=r"(r[1]), "=r"(r[2]), "=r"(r[3]) : "r"(addr));
}
__device__ __forceinline__ void mma_bf16(float (&c)[4], const uint32_t (&a)[4],
                                         uint32_t b0, uint32_t b1) {
    asm volatile(
        "mma.sync.aligned.m16n8k16.row.col.f32.bf16.bf16.f32 "
        "{%0,%1,%2,%3}, {%4,%5,%6,%7}, {%8,%9}, {%0,%1,%2,%3};"
        : "+f"(c[0]), "+f"(c[1]), "+f"(c[2]), "+f"(c[3])
        : "r"(a[0]), "r"(a[1]), "r"(a[2]), "r"(a[3]), "r"(b0), "r"(b1));
}
// Named barrier over one half (256 threads). id = 1 + half.
__device__ __forceinline__ void barh(int id) {
    asm volatile("bar.sync %0, 256;" :: "r"(id) : "memory");
}

// ---------------------------------------------------------------------------
// Helpers
// ---------------------------------------------------------------------------
__device__ __forceinline__ void split_pack(float a, float b, uint32_t& hi, uint32_t& lo) {
    __nv_bfloat162 h2 = __floats2bfloat162_rn(a, b);
    float2 hf = __bfloat1622float2(h2);
    __nv_bfloat162 l2 = __floats2bfloat162_rn(a - hf.x, b - hf.y);
    hi = *reinterpret_cast<uint32_t*>(&h2);
    lo = *reinterpret_cast<uint32_t*>(&l2);
}
__device__ __forceinline__ float tanh_fast(float x) {
    float e = __expf(2.0f * x);
    return 1.0f - __fdividef(2.0f, e + 1.0f);
}

// ---------------------------------------------------------------------------
// Merged 3-term GEMM: acc += Ah@Bh + Al@Bh + Ah@Bl over ksteps k-chunks of 16.
// Warp tile 32x32 (2 m-subtiles x 2 n-subtiles x 2 halves of n8).
// ---------------------------------------------------------------------------
__device__ __forceinline__ void gemm3(float (&acc)[8][4],
                                      uint32_t aH, uint32_t aL,
                                      uint32_t bH, uint32_t bL, int ksteps) {
    for (int kk = 0; kk < ksteps; kk++) {
        uint32_t ah0[4], ah1[4], al0[4], al1[4];
        uint32_t b0[4], b1[4], c0[4], c1[4];
        ldsm_x4(ah0, aH);
        ldsm_x4_t(b0, bH);
        ldsm_x4(ah1, aH + 16 * PK * 2);
        ldsm_x4_t(b1, bH + 32);
        ldsm_x4(al0, aL);
        ldsm_x4(al1, aL + 16 * PK * 2);
        ldsm_x4_t(c0, bL);
        ldsm_x4_t(c1, bL + 32);
        mma_bf16(acc[0], ah0, b0[0], b0[1]);
        mma_bf16(acc[1], ah0, b0[2], b0[3]);
        mma_bf16(acc[4], ah1, b0[0], b0[1]);
        mma_bf16(acc[5], ah1, b0[2], b0[3]);
        mma_bf16(acc[2], ah0, b1[0], b1[1]);
        mma_bf16(acc[3], ah0, b1[2], b1[3]);
        mma_bf16(acc[6], ah1, b1[0], b1[1]);
        mma_bf16(acc[7], ah1, b1[2], b1[3]);
        mma_bf16(acc[0], al0, b0[0], b0[1]);
        mma_bf16(acc[1], al0, b0[2], b0[3]);
        mma_bf16(acc[4], al1, b0[0], b0[1]);
        mma_bf16(acc[5], al1, b0[2], b0[3]);
        mma_bf16(acc[2], al0, b1[0], b1[1]);
        mma_bf16(acc[3], al0, b1[2], b1[3]);
        mma_bf16(acc[6], al1, b1[0], b1[1]);
        mma_bf16(acc[7], al1, b1[2], b1[3]);
        mma_bf16(acc[0], ah0, c0[0], c0[1]);
        mma_bf16(acc[1], ah0, c0[2], c0[3]);
        mma_bf16(acc[4], ah1, c0[0], c0[1]);
        mma_bf16(acc[5], ah1, c0[2], c0[3]);
        mma_bf16(acc[2], ah0, c1[0], c1[1]);
        mma_bf16(acc[3], ah0, c1[2], c1[3]);
        mma_bf16(acc[6], ah1, c1[0], c1[1]);
        mma_bf16(acc[7], ah1, c1[2], c1[3]);

        aH += 32; aL += 32;
        bH += 16 * PK * 2; bL += 16 * PK * 2;
    }
}

// ---------------------------------------------------------------------------
// Persistent fused kernel, split-half pipelined:
// each CTA = two independent 8-warp halves, each processing its own stream of
// 64-row tiles with private named barriers -> one half's memory phases overlap
// the other half's MMA phases.
// ATOMS: D1 = af@W_cf (+b_cf) -> afh; msg = b_df*afh; D2 = msg@W_fc;
//        out = af - tanh(D2)
// PAIRS: D1 = dist@W_df (+b_df); msg = D1 * afh[dmj]; D2 = msg@W_fc;
//        out[dmi] += tanh(D2)  (run-length-reduced atomics)
// ---------------------------------------------------------------------------
template <bool PAIRS, int K1>
__global__ void __launch_bounds__(THREADS, 1)
dtnn_mma(const float* __restrict__ A,
         const float* __restrict__ W1,
         const float* __restrict__ W2,
         const float* __restrict__ bias1,
         const float* __restrict__ bdf,
         float* __restrict__ afh,
         const int* __restrict__ dmj,
         const int* __restrict__ dmi,
         float* __restrict__ out,
         int M, int ntiles)
{
    extern __shared__ char sm[];
    const uint32_t smb = smem_to_u32(sm);
    const int tid = threadIdx.x;
    const int lane = tid & 31;
    const int w = tid >> 5;          // 0..15
    const int h = w >> 3;            // half: warps 0-7 / 8-15
    const int wl = w & 7;            // warp-in-half
    const int wm2 = wl & 1;          // row block (32 rows of 64)
    const int wn = wl >> 1;          // col block (32 cols of 128)
    const int lt = tid & 255;        // thread-in-half (contiguous)
    const int bar_id = 1 + h;

    char* smA = sm + OFF_A + h * TILE_B;       // half-private A block
    float* s_outF = reinterpret_cast<float*>(smA);
    int* s_dmj = reinterpret_cast<int*>(sm + OFF_IDX) + h * 64;
    int* s_dmi = reinterpret_cast<int*>(sm + OFF_IDX + 512) + h * 64;

    // ---- stage weights once per CTA (hi/lo split, padded rows) ----
    for (int i = tid; i < 4096; i += THREADS) {
        const int k = i >> 5;
        const int n4 = (i & 31) << 2;
        float4 v = make_float4(0.f, 0.f, 0.f, 0.f);
        if (k < K1) v = reinterpret_cast<const float4*>(W1)[(k * 128 + n4) >> 2];
        uint32_t h01, l01, h23, l23;
        split_pack(v.x, v.y, h01, l01);
        split_pack(v.z, v.w, h23, l23);
        *reinterpret_cast<uint2*>(sm + OFF_B1H + ((size_t)k * PK + n4) * 2) = make_uint2(h01, h23);
        *reinterpret_cast<uint2*>(sm + OFF_B1L + ((size_t)k * PK + n4) * 2) = make_uint2(l01, l23);
        float4 v2 = reinterpret_cast<const float4*>(W2)[(k * 128 + n4) >> 2];
        split_pack(v2.x, v2.y, h01, l01);
        split_pack(v2.z, v2.w, h23, l23);
        *reinterpret_cast<uint2*>(sm + OFF_B2H + ((size_t)k * PK + n4) * 2) = make_uint2(h01, h23);
        *reinterpret_cast<uint2*>(sm + OFF_B2L + ((size_t)k * PK + n4) * 2) = make_uint2(l01, l23);
    }
    __syncthreads();

    // ---- lane geometry ----
    const int g = lane >> 3, r8 = lane & 7;
    const uint32_t aOff =
        (uint32_t)(((wm2 * 32 + (g & 1) * 8 + r8) * PK + (g >> 1) * 8) * 2);
    const uint32_t bOff =
        (uint32_t)((((g & 1) * 8 + r8) * PK + (g >> 1) * 8) * 2) + (uint32_t)wn * 64;
    const int lr = wm2 * 32 + (lane >> 2);        // local epilogue row (0..63 space)
    const int q2 = (lane & 3) * 2;
    const int cBase = wn * 32;
    constexpr int KS1 = (K1 + 15) / 16;

    const uint32_t uAH = smb + OFF_A + h * TILE_B;
    const uint32_t uAL = uAH + TILE_B / 2;
    const uint32_t uB1H = smb + OFF_B1H, uB1L = smb + OFF_B1L;
    const uint32_t uB2H = smb + OFF_B2H, uB2L = smb + OFF_B2L;

    for (int t = blockIdx.x * 2 + h; t < ntiles; t += gridDim.x * 2) {
        barh(bar_id);   // A-block reuse guard (prev iter readers done)
        const int m0 = t << 6;   // 64-row tiles

        // ---- stage A tile: 64 rows, bf16 hi/lo ----
        if (PAIRS) {
            const float* src = A + (size_t)m0 * K1;
            for (int i = lt; i < 64 * (K1 / 4); i += 256) {
                const int rr = i / (K1 / 4);
                const int c0 = (i - rr * (K1 / 4)) * 4;
                float4 v = reinterpret_cast<const float4*>(src)[i];
                uint32_t h01, l01, h23, l23;
                split_pack(v.x, v.y, h01, l01);
                split_pack(v.z, v.w, h23, l23);
                *reinterpret_cast<uint2*>(smA + ((size_t)rr * PK + c0) * 2) = make_uint2(h01, h23);
                *reinterpret_cast<uint2*>(smA + TILE_B / 2 + ((size_t)rr * PK + c0) * 2) = make_uint2(l01, l23);
            }
            constexpr int PADN = KS1 * 16 - K1;
            if (PADN > 0) {
                for (int i = lt; i < 64 * PADN; i += 256) {
                    const int rr = i / PADN;
                    const int cc = K1 + (i - rr * PADN);
                    reinterpret_cast<__nv_bfloat16*>(smA)[rr * PK + cc] = __float2bfloat16(0.f);
                    reinterpret_cast<__nv_bfloat16*>(smA + TILE_B / 2)[rr * PK + cc] = __float2bfloat16(0.f);
                }
            }
            if (lt < 64) {
                s_dmj[lt] = dmj[m0 + lt];
                s_dmi[lt] = dmi[m0 + lt];
            }
        } else {
            for (int i = lt; i < 2048; i += 256) {
                const int rr = i >> 5;
                const int c4 = (i & 31) << 2;
                float4 v = make_float4(0.f, 0.f, 0.f, 0.f);
                if (m0 + rr < M)
                    v = *reinterpret_cast<const float4*>(A + (size_t)(m0 + rr) * 128 + c4);
                uint32_t h01, l01, h23, l23;
                split_pack(v.x, v.y, h01, l01);
                split_pack(v.z, v.w, h23, l23);
                *reinterpret_cast<uint2*>(smA + ((size_t)rr * PK + c4) * 2) = make_uint2(h01, h23);
                *reinterpret_cast<uint2*>(smA + TILE_B / 2 + ((size_t)rr * PK + c4) * 2) = make_uint2(l01, l23);
            }
        }
        barh(bar_id);

        // hoist gather indices (hidden under GEMM1)
        int jrow[4];
        if (PAIRS) {
#pragma unroll
            for (int s = 0; s < 4; s++) jrow[s] = s_dmj[lr + s * 8];
        }

        // ---- GEMM1 ----
        float acc[8][4];
#pragma unroll
        for (int j = 0; j < 8; j++)
#pragma unroll
            for (int i = 0; i < 4; i++) acc[j][i] = 0.f;
        gemm3(acc, uAH + aOff, uAL + aOff, uB1H + bOff, uB1L + bOff, KS1);

        // ---- Epilogue 1 (compute msg in-place in acc) ----
#pragma unroll
        for (int mt = 0; mt < 2; mt++) {
#pragma unroll
            for (int jh = 0; jh < 4; jh++) {
                const int ai = mt * 4 + jh;
                const int col = cBase + jh * 8 + q2;
                const float2 b1 = __ldg(reinterpret_cast<const float2*>(bias1 + col));
                float v0 = acc[ai][0] + b1.x, v1 = acc[ai][1] + b1.y;
                float v2 = acc[ai][2] + b1.x, v3 = acc[ai][3] + b1.y;
                if (PAIRS) {
                    const float2 gA = __ldg(reinterpret_cast<const float2*>(
                        afh + (size_t)jrow[mt * 2] * 128 + col));
                    const float2 gB = __ldg(reinterpret_cast<const float2*>(
                        afh + (size_t)jrow[mt * 2 + 1] * 128 + col));
                    v0 *= gA.x; v1 *= gA.y; v2 *= gB.x; v3 *= gB.y;
                } else {
                    const int rA = m0 + lr + mt * 16;
                    if (rA < M)
                        *reinterpret_cast<float2*>(afh + (size_t)rA * 128 + col) = make_float2(v0, v1);
                    if (rA + 8 < M)
                        *reinterpret_cast<float2*>(afh + (size_t)(rA + 8) * 128 + col) = make_float2(v2, v3);
                    const float2 bd = __ldg(reinterpret_cast<const float2*>(bdf + col));
                    v0 *= bd.x; v1 *= bd.y; v2 *= bd.x; v3 *= bd.y;
                }
                acc[ai][0] = v0; acc[ai][1] = v1; acc[ai][2] = v2; acc[ai][3] = v3;
            }
        }
        barh(bar_id);   // all half-warps done reading A tiles

        // ---- exchange msg through A block (hi/lo) ----
#pragma unroll
        for (int mt = 0; mt < 2; mt++) {
            const int r0 = lr + mt * 16;
#pragma unroll
            for (int jh = 0; jh < 4; jh++) {
                const int ai = mt * 4 + jh;
                const int col = cBase + jh * 8 + q2;
                uint32_t hi, lo;
                split_pack(acc[ai][0], acc[ai][1], hi, lo);
                *reinterpret_cast<uint32_t*>(smA + ((size_t)r0 * PK + col) * 2) = hi;
                *reinterpret_cast<uint32_t*>(smA + TILE_B / 2 + ((size_t)r0 * PK + col) * 2) = lo;
                split_pack(acc[ai][2], acc[ai][3], hi, lo);
                *reinterpret_cast<uint32_t*>(smA + ((size_t)(r0 + 8) * PK + col) * 2) = hi;
                *reinterpret_cast<uint32_t*>(smA + TILE_B / 2 + ((size_t)(r0 + 8) * PK + col) * 2) = lo;
            }
        }
        barh(bar_id);

        // ---- GEMM2 ----
#pragma unroll
        for (int j = 0; j < 8; j++)
#pragma unroll
            for (int i = 0; i < 4; i++) acc[j][i] = 0.f;
        gemm3(acc, uAH + aOff, uAL + aOff, uB2H + bOff, uB2L + bOff, 8);

        // ---- Epilogue 2 ----
        if (!PAIRS) {
#pragma unroll
            for (int mt = 0; mt < 2; mt++) {
#pragma unroll
                for (int jh = 0; jh < 4; jh++) {
                    const int ai = mt * 4 + jh;
                    const int col = cBase + jh * 8 + q2;
                    const int rA = m0 + lr + mt * 16;
                    if (rA < M) {
                        const float2 af = __ldg(reinterpret_cast<const float2*>(
                            A + (size_t)rA * 128 + col));
                        *reinterpret_cast<float2*>(out + (size_t)rA * 128 + col) =
                            make_float2(af.x - tanh_fast(acc[ai][0]),
                                        af.y - tanh_fast(acc[ai][1]));
                    }
                    if (rA + 8 < M) {
                        const float2 af = __ldg(reinterpret_cast<const float2*>(
                            A + (size_t)(rA + 8) * 128 + col));
                        *reinterpret_cast<float2*>(out + (size_t)(rA + 8) * 128 + col) =
                            make_float2(af.x - tanh_fast(acc[ai][2]),
                                        af.y - tanh_fast(acc[ai][3]));
                    }
                }
            }
        } else {
            barh(bar_id);   // half-warps done reading msg before fp32 overlay
#pragma unroll
            for (int mt = 0; mt < 2; mt++) {
                const int r0 = lr + mt * 16;
#pragma unroll
                for (int jh = 0; jh < 4; jh++) {
                    const int ai = mt * 4 + jh;
                    const int col = cBase + jh * 8 + q2;
                    *reinterpret_cast<float2*>(s_outF + r0 * OUT_STRIDE + col) =
                        make_float2(tanh_fast(acc[ai][0]), tanh_fast(acc[ai][1]));
                    *reinterpret_cast<float2*>(s_outF + (r0 + 8) * OUT_STRIDE + col) =
                        make_float2(tanh_fast(acc[ai][2]), tanh_fast(acc[ai][3]));
                }
            }
            barh(bar_id);
            // run-length segment reduction (dmi sorted): ~1 atomic per run
            const int c = lt & 127;
            const int r0 = (lt >> 7) << 5;   // 2 segments x 32 rows
            float racc = 0.f;
            int cur = s_dmi[r0];
            for (int rr = r0; rr < r0 + 32; rr++) {
                const int ir = s_dmi[rr];
                if (ir != cur) {
                    atomicAdd(out + (size_t)cur * 128 + c, racc);
                    racc = 0.f;
                    cur = ir;
                }
                racc += s_outF[rr * OUT_STRIDE + c];
            }
            atomicAdd(out + (size_t)cur * 128 + c, racc);
        }
    }
}

// ---------------------------------------------------------------------------
extern "C" void kernel_launch(void* const* d_in, const int* in_sizes, int n_in,
                              void* d_out, int out_size)
{
    const float* atom_features = (const float*)d_in[0];
    const float* distance      = (const float*)d_in[1];
    // d_in[2] = atom_membership (unused by the computation)
    const int*   dmi           = (const int*)d_in[3];
    const int*   dmj           = (const int*)d_in[4];
    const float* W_cf          = (const float*)d_in[5];
    const float* W_df          = (const float*)d_in[6];
    const float* W_fc          = (const float*)d_in[7];
    const float* b_cf          = (const float*)d_in[8];
    const float* b_df          = (const float*)d_in[9];
    float* out = (float*)d_out;

    float* afh = nullptr;
    cudaGetSymbolAddress((void**)&afh, g_afh);

    cudaFuncSetAttribute(dtnn_mma<false, 128>,
                         cudaFuncAttributeMaxDynamicSharedMemorySize, SMEM_SZ);
    cudaFuncSetAttribute(dtnn_mma<true, 100>,
                         cudaFuncAttributeMaxDynamicSharedMemorySize, SMEM_SZ);

    const int atom_tiles = (N_ATOMS + 63) / 64;   // 782 (64-row tiles)
    const int pair_tiles = N_PAIRS / 64;          // 12500

    // 1. Atom path: afh + out init (writes every output element)
    dtnn_mma<false, 128><<<152, THREADS, SMEM_SZ>>>(
        atom_features, W_cf, W_fc, b_cf, b_df, afh, nullptr, nullptr,
        out, N_ATOMS, atom_tiles);

    // 2. Pair path: msgs + run-length-reduced segment sum
    dtnn_mma<true, 100><<<152, THREADS, SMEM_SZ>>>(
        distance, W_df, W_fc, b_df, nullptr, afh, dmj, dmi,
        out, N_PAIRS, pair_tiles);
}

// round 16
// speedup vs baseline: 3.8042x; 1.2316x over previous
#include <cuda_runtime.h>
#include <cuda_bf16.h>
#include <cstdint>
#include <math.h>

#define N_ATOMS 50000
#define N_PAIRS 800000

// ---------------------------------------------------------------------------
// Device scratch (no cudaMalloc allowed)
// ---------------------------------------------------------------------------
__device__ float g_afh[(size_t)N_ATOMS * 128];   // 25.6 MB, L2-resident

// ---------------------------------------------------------------------------
// SMEM layout (dynamic): bf16 tiles padded to PK=136 cols (272B rows ->
// conflict-free ldmatrix/STS across 8-row strides).
// B tiles now stored [n][k] (k-contiguous) so ALL B fragment loads are
// non-transposed ldmatrix (no .trans wavefront amplification).
// A region: per-half blocks; half h owns [OFF_A + h*TILE_B, +TILE_B):
//   hi rows 0..63 at +0, lo rows 0..63 at +TILE_B/2. fp32 out-tile overlays.
// ---------------------------------------------------------------------------
constexpr int PK = 136;
constexpr int TILE_B = 128 * PK * 2;            // 34816 B
constexpr int OFF_B1H = 0;
constexpr int OFF_B1L = TILE_B;
constexpr int OFF_B2H = 2 * TILE_B;
constexpr int OFF_B2L = 3 * TILE_B;
constexpr int OFF_A   = 4 * TILE_B;             // two per-half blocks
constexpr int OFF_IDX = OFF_A + 2 * TILE_B;
constexpr int SMEM_SZ = OFF_IDX + 1024;         // 209920
constexpr int OUT_STRIDE = 132;                 // fp32 out-tile padded stride
constexpr int THREADS = 512;

// ---------------------------------------------------------------------------
// PTX primitives (baseline ISA: sm_80+, compiles for plain sm_103)
// ---------------------------------------------------------------------------
__device__ __forceinline__ uint32_t smem_to_u32(const void* p) {
    uint32_t a;
    asm("{ .reg .u64 t; cvta.to.shared.u64 t, %1; cvt.u32.u64 %0, t; }" : "=r"(a) : "l"(p));
    return a;
}
__device__ __forceinline__ void ldsm_x4(uint32_t (&r)[4], uint32_t addr) {
    asm volatile("ldmatrix.sync.aligned.m8n8.x4.shared.b16 {%0,%1,%2,%3}, [%4];"
                 : "=r"(r[0]), "=r"(r[1]), "=r"(r[2]), "=r"(r[3]) : "r"(addr));
}
__device__ __forceinline__ void mma_bf16(float (&c)[4], const uint32_t (&a)[4],
                                         uint32_t b0, uint32_t b1) {
    asm volatile(
        "mma.sync.aligned.m16n8k16.row.col.f32.bf16.bf16.f32 "
        "{%0,%1,%2,%3}, {%4,%5,%6,%7}, {%8,%9}, {%0,%1,%2,%3};"
        : "+f"(c[0]), "+f"(c[1]), "+f"(c[2]), "+f"(c[3])
        : "r"(a[0]), "r"(a[1]), "r"(a[2]), "r"(a[3]), "r"(b0), "r"(b1));
}
// Named barrier over one half (256 threads). id = 1 + half.
__device__ __forceinline__ void barh(int id) {
    asm volatile("bar.sync %0, 256;" :: "r"(id) : "memory");
}

// ---------------------------------------------------------------------------
// Helpers
// ---------------------------------------------------------------------------
__device__ __forceinline__ void split_pack(float a, float b, uint32_t& hi, uint32_t& lo) {
    __nv_bfloat162 h2 = __floats2bfloat162_rn(a, b);
    float2 hf = __bfloat1622float2(h2);
    __nv_bfloat162 l2 = __floats2bfloat162_rn(a - hf.x, b - hf.y);
    hi = *reinterpret_cast<uint32_t*>(&h2);
    lo = *reinterpret_cast<uint32_t*>(&l2);
}
__device__ __forceinline__ float tanh_fast(float x) {
    float e = __expf(2.0f * x);
    return 1.0f - __fdividef(2.0f, e + 1.0f);
}

// ---------------------------------------------------------------------------
// Merged 3-term GEMM: acc += Ah@Bh + Al@Bh + Ah@Bl over ksteps k-chunks of 16.
// Warp tile 32x32. B fragments via NON-trans ldmatrix on [n][k] tiles:
// b[0],b[1] = n-tile0 (k lo/hi half), b[2],b[3] = n-tile1.
// ---------------------------------------------------------------------------
__device__ __forceinline__ void gemm3(float (&acc)[8][4],
                                      uint32_t aH, uint32_t aL,
                                      uint32_t bH, uint32_t bL, int ksteps) {
    for (int kk = 0; kk < ksteps; kk++) {
        uint32_t ah0[4], ah1[4], al0[4], al1[4];
        uint32_t b0[4], b1[4], c0[4], c1[4];
        ldsm_x4(ah0, aH);
        ldsm_x4(b0, bH);
        ldsm_x4(ah1, aH + 16 * PK * 2);
        ldsm_x4(b1, bH + 16 * PK * 2);
        ldsm_x4(al0, aL);
        ldsm_x4(al1, aL + 16 * PK * 2);
        ldsm_x4(c0, bL);
        ldsm_x4(c1, bL + 16 * PK * 2);
        mma_bf16(acc[0], ah0, b0[0], b0[1]);
        mma_bf16(acc[1], ah0, b0[2], b0[3]);
        mma_bf16(acc[4], ah1, b0[0], b0[1]);
        mma_bf16(acc[5], ah1, b0[2], b0[3]);
        mma_bf16(acc[2], ah0, b1[0], b1[1]);
        mma_bf16(acc[3], ah0, b1[2], b1[3]);
        mma_bf16(acc[6], ah1, b1[0], b1[1]);
        mma_bf16(acc[7], ah1, b1[2], b1[3]);
        mma_bf16(acc[0], al0, b0[0], b0[1]);
        mma_bf16(acc[1], al0, b0[2], b0[3]);
        mma_bf16(acc[4], al1, b0[0], b0[1]);
        mma_bf16(acc[5], al1, b0[2], b0[3]);
        mma_bf16(acc[2], al0, b1[0], b1[1]);
        mma_bf16(acc[3], al0, b1[2], b1[3]);
        mma_bf16(acc[6], al1, b1[0], b1[1]);
        mma_bf16(acc[7], al1, b1[2], b1[3]);
        mma_bf16(acc[0], ah0, c0[0], c0[1]);
        mma_bf16(acc[1], ah0, c0[2], c0[3]);
        mma_bf16(acc[4], ah1, c0[0], c0[1]);
        mma_bf16(acc[5], ah1, c0[2], c0[3]);
        mma_bf16(acc[2], ah0, c1[0], c1[1]);
        mma_bf16(acc[3], ah0, c1[2], c1[3]);
        mma_bf16(acc[6], ah1, c1[0], c1[1]);
        mma_bf16(acc[7], ah1, c1[2], c1[3]);

        aH += 32; aL += 32;
        bH += 32; bL += 32;   // k advances 16 bf16 = 32 B in [n][k] layout
    }
}

// ---------------------------------------------------------------------------
// Persistent fused kernel, split-half + software-pipelined A staging:
// next tile's A rows (and dmi/dmj) are prefetched into registers after GEMM2
// so the LDG latency overlaps epilogue 2 / atomics.
// ATOMS: D1 = af@W_cf (+b_cf) -> afh; msg = b_df*afh; D2 = msg@W_fc;
//        out = af - tanh(D2)
// PAIRS: D1 = dist@W_df (+b_df); msg = D1 * afh[dmj]; D2 = msg@W_fc;
//        out[dmi] += tanh(D2)  (run-length-reduced atomics)
// ---------------------------------------------------------------------------
template <bool PAIRS, int K1>
__global__ void __launch_bounds__(THREADS, 1)
dtnn_mma(const float* __restrict__ A,
         const float* __restrict__ W1,
         const float* __restrict__ W2,
         const float* __restrict__ bias1,
         const float* __restrict__ bdf,
         float* __restrict__ afh,
         const int* __restrict__ dmj,
         const int* __restrict__ dmi,
         float* __restrict__ out,
         int M, int ntiles)
{
    extern __shared__ char sm[];
    const uint32_t smb = smem_to_u32(sm);
    const int tid = threadIdx.x;
    const int lane = tid & 31;
    const int w = tid >> 5;          // 0..15
    const int h = w >> 3;            // half: warps 0-7 / 8-15
    const int wl = w & 7;            // warp-in-half
    const int wm2 = wl & 1;          // row block (32 rows of 64)
    const int wn = wl >> 1;          // col block (32 cols of 128)
    const int lt = tid & 255;        // thread-in-half (contiguous)
    const int bar_id = 1 + h;
    constexpr int KS1 = (K1 + 15) / 16;
    constexpr int NPF = PAIRS ? 7 : 8;               // prefetch float4s/thread
    constexpr int NF4 = PAIRS ? 64 * (K1 / 4) : 2048;

    char* smA = sm + OFF_A + h * TILE_B;       // half-private A block
    float* s_outF = reinterpret_cast<float*>(smA);
    int* s_dmj = reinterpret_cast<int*>(sm + OFF_IDX) + h * 64;
    int* s_dmi = reinterpret_cast<int*>(sm + OFF_IDX + 512) + h * 64;

    // ---- stage weights once per CTA, TRANSPOSED to [n][k], hi/lo split ----
    for (int i = tid; i < 4096; i += THREADS) {
        const int k4 = (i >> 7) << 2;   // 0,4,...,124
        const int n  = i & 127;
        float w1v[4], w2v[4];
#pragma unroll
        for (int j = 0; j < 4; j++) {
            const int k = k4 + j;
            w1v[j] = (k < K1) ? W1[k * 128 + n] : 0.f;
            w2v[j] = W2[k * 128 + n];
        }
        uint32_t h01, l01, h23, l23;
        split_pack(w1v[0], w1v[1], h01, l01);
        split_pack(w1v[2], w1v[3], h23, l23);
        *reinterpret_cast<uint2*>(sm + OFF_B1H + ((size_t)n * PK + k4) * 2) = make_uint2(h01, h23);
        *reinterpret_cast<uint2*>(sm + OFF_B1L + ((size_t)n * PK + k4) * 2) = make_uint2(l01, l23);
        split_pack(w2v[0], w2v[1], h01, l01);
        split_pack(w2v[2], w2v[3], h23, l23);
        *reinterpret_cast<uint2*>(sm + OFF_B2H + ((size_t)n * PK + k4) * 2) = make_uint2(h01, h23);
        *reinterpret_cast<uint2*>(sm + OFF_B2L + ((size_t)n * PK + k4) * 2) = make_uint2(l01, l23);
    }
    __syncthreads();

    // ---- lane geometry ----
    const int g = lane >> 3, r8 = lane & 7;
    const uint32_t aOff =
        (uint32_t)(((wm2 * 32 + (g & 1) * 8 + r8) * PK + (g >> 1) * 8) * 2);
    // [n][k] B: lanes 0-7 -> (n+r8, k), 8-15 -> (n+r8, k+8),
    //           16-23 -> (n+8+r8, k), 24-31 -> (n+8+r8, k+8)
    const uint32_t bOff =
        (uint32_t)(((wn * 32 + ((lane >> 4) & 1) * 8 + r8) * PK + ((lane >> 3) & 1) * 8) * 2);
    const int lr = wm2 * 32 + (lane >> 2);        // local epilogue row (0..63)
    const int q2 = (lane & 3) * 2;
    const int cBase = wn * 32;

    const uint32_t uAH = smb + OFF_A + h * TILE_B;
    const uint32_t uAL = uAH + TILE_B / 2;
    const uint32_t uB1H = smb + OFF_B1H, uB1L = smb + OFF_B1L;
    const uint32_t uB2H = smb + OFF_B2H, uB2L = smb + OFF_B2L;

    // ---- prefetch state ----
    float4 pf[NPF];
    int pfj = 0, pfi = 0;

    auto ldA = [&](int tt) {
        const int mm0 = tt << 6;
        if (PAIRS) {
            const float4* src = reinterpret_cast<const float4*>(A + (size_t)mm0 * K1);
#pragma unroll
            for (int p = 0; p < NPF; p++) {
                const int idx = lt + p * 256;
                if (idx < NF4) pf[p] = src[idx];
            }
            if (lt < 64) { pfj = dmj[mm0 + lt]; pfi = dmi[mm0 + lt]; }
        } else {
#pragma unroll
            for (int p = 0; p < NPF; p++) {
                const int idx = lt + p * 256;
                const int rr = idx >> 5, c4 = (idx & 31) << 2;
                pf[p] = (mm0 + rr < M)
                    ? *reinterpret_cast<const float4*>(A + (size_t)(mm0 + rr) * 128 + c4)
                    : make_float4(0.f, 0.f, 0.f, 0.f);
            }
        }
    };
    auto stA = [&]() {
        if (PAIRS) {
#pragma unroll
            for (int p = 0; p < NPF; p++) {
                const int idx = lt + p * 256;
                if (idx < NF4) {
                    const int rr = idx / (K1 / 4);
                    const int c0 = (idx - rr * (K1 / 4)) * 4;
                    uint32_t h01, l01, h23, l23;
                    split_pack(pf[p].x, pf[p].y, h01, l01);
                    split_pack(pf[p].z, pf[p].w, h23, l23);
                    *reinterpret_cast<uint2*>(smA + ((size_t)rr * PK + c0) * 2) = make_uint2(h01, h23);
                    *reinterpret_cast<uint2*>(smA + TILE_B / 2 + ((size_t)rr * PK + c0) * 2) = make_uint2(l01, l23);
                }
            }
            constexpr int PADN = KS1 * 16 - K1;   // re-zero pad (msg overwrote)
            for (int i2 = lt; i2 < 64 * PADN; i2 += 256) {
                const int rr = i2 / PADN;
                const int cc = K1 + (i2 - rr * PADN);
                reinterpret_cast<__nv_bfloat16*>(smA)[rr * PK + cc] = __float2bfloat16(0.f);
                reinterpret_cast<__nv_bfloat16*>(smA + TILE_B / 2)[rr * PK + cc] = __float2bfloat16(0.f);
            }
            if (lt < 64) { s_dmj[lt] = pfj; s_dmi[lt] = pfi; }
        } else {
#pragma unroll
            for (int p = 0; p < NPF; p++) {
                const int idx = lt + p * 256;
                const int rr = idx >> 5, c4 = (idx & 31) << 2;
                uint32_t h01, l01, h23, l23;
                split_pack(pf[p].x, pf[p].y, h01, l01);
                split_pack(pf[p].z, pf[p].w, h23, l23);
                *reinterpret_cast<uint2*>(smA + ((size_t)rr * PK + c4) * 2) = make_uint2(h01, h23);
                *reinterpret_cast<uint2*>(smA + TILE_B / 2 + ((size_t)rr * PK + c4) * 2) = make_uint2(l01, l23);
            }
        }
    };

    const int tstep = gridDim.x * 2;
    int t = blockIdx.x * 2 + h;
    if (t < ntiles) ldA(t);

    for (; t < ntiles; t += tstep) {
        barh(bar_id);   // A-block reuse guard (prev iter readers done)
        stA();
        barh(bar_id);
        const int m0 = t << 6;

        // hoist gather indices (hidden under GEMM1)
        int jrow[4];
        if (PAIRS) {
#pragma unroll
            for (int s = 0; s < 4; s++) jrow[s] = s_dmj[lr + s * 8];
        }

        // ---- GEMM1 ----
        float acc[8][4];
#pragma unroll
        for (int j = 0; j < 8; j++)
#pragma unroll
            for (int i = 0; i < 4; i++) acc[j][i] = 0.f;
        gemm3(acc, uAH + aOff, uAL + aOff, uB1H + bOff, uB1L + bOff, KS1);

        // ---- Epilogue 1 (compute msg in-place in acc) ----
#pragma unroll
        for (int mt = 0; mt < 2; mt++) {
#pragma unroll
            for (int jh = 0; jh < 4; jh++) {
                const int ai = mt * 4 + jh;
                const int col = cBase + jh * 8 + q2;
                const float2 b1 = __ldg(reinterpret_cast<const float2*>(bias1 + col));
                float v0 = acc[ai][0] + b1.x, v1 = acc[ai][1] + b1.y;
                float v2 = acc[ai][2] + b1.x, v3 = acc[ai][3] + b1.y;
                if (PAIRS) {
                    const float2 gA = __ldg(reinterpret_cast<const float2*>(
                        afh + (size_t)jrow[mt * 2] * 128 + col));
                    const float2 gB = __ldg(reinterpret_cast<const float2*>(
                        afh + (size_t)jrow[mt * 2 + 1] * 128 + col));
                    v0 *= gA.x; v1 *= gA.y; v2 *= gB.x; v3 *= gB.y;
                } else {
                    const int rA = m0 + lr + mt * 16;
                    if (rA < M)
                        *reinterpret_cast<float2*>(afh + (size_t)rA * 128 + col) = make_float2(v0, v1);
                    if (rA + 8 < M)
                        *reinterpret_cast<float2*>(afh + (size_t)(rA + 8) * 128 + col) = make_float2(v2, v3);
                    const float2 bd = __ldg(reinterpret_cast<const float2*>(bdf + col));
                    v0 *= bd.x; v1 *= bd.y; v2 *= bd.x; v3 *= bd.y;
                }
                acc[ai][0] = v0; acc[ai][1] = v1; acc[ai][2] = v2; acc[ai][3] = v3;
            }
        }
        barh(bar_id);   // all half-warps done reading A tiles

        // ---- exchange msg through A block (hi/lo) ----
#pragma unroll
        for (int mt = 0; mt < 2; mt++) {
            const int r0 = lr + mt * 16;
#pragma unroll
            for (int jh = 0; jh < 4; jh++) {
                const int ai = mt * 4 + jh;
                const int col = cBase + jh * 8 + q2;
                uint32_t hi, lo;
                split_pack(acc[ai][0], acc[ai][1], hi, lo);
                *reinterpret_cast<uint32_t*>(smA + ((size_t)r0 * PK + col) * 2) = hi;
                *reinterpret_cast<uint32_t*>(smA + TILE_B / 2 + ((size_t)r0 * PK + col) * 2) = lo;
                split_pack(acc[ai][2], acc[ai][3], hi, lo);
                *reinterpret_cast<uint32_t*>(smA + ((size_t)(r0 + 8) * PK + col) * 2) = hi;
                *reinterpret_cast<uint32_t*>(smA + TILE_B / 2 + ((size_t)(r0 + 8) * PK + col) * 2) = lo;
            }
        }
        barh(bar_id);

        // ---- GEMM2 ----
#pragma unroll
        for (int j = 0; j < 8; j++)
#pragma unroll
            for (int i = 0; i < 4; i++) acc[j][i] = 0.f;
        gemm3(acc, uAH + aOff, uAL + aOff, uB2H + bOff, uB2L + bOff, 8);

        // ---- prefetch next tile (LDG latency overlaps epilogue 2) ----
        if (t + tstep < ntiles) ldA(t + tstep);

        // ---- Epilogue 2 ----
        if (!PAIRS) {
#pragma unroll
            for (int mt = 0; mt < 2; mt++) {
#pragma unroll
                for (int jh = 0; jh < 4; jh++) {
                    const int ai = mt * 4 + jh;
                    const int col = cBase + jh * 8 + q2;
                    const int rA = m0 + lr + mt * 16;
                    if (rA < M) {
                        const float2 af = __ldg(reinterpret_cast<const float2*>(
                            A + (size_t)rA * 128 + col));
                        *reinterpret_cast<float2*>(out + (size_t)rA * 128 + col) =
                            make_float2(af.x - tanh_fast(acc[ai][0]),
                                        af.y - tanh_fast(acc[ai][1]));
                    }
                    if (rA + 8 < M) {
                        const float2 af = __ldg(reinterpret_cast<const float2*>(
                            A + (size_t)(rA + 8) * 128 + col));
                        *reinterpret_cast<float2*>(out + (size_t)(rA + 8) * 128 + col) =
                            make_float2(af.x - tanh_fast(acc[ai][2]),
                                        af.y - tanh_fast(acc[ai][3]));
                    }
                }
            }
        } else {
            barh(bar_id);   // half-warps done reading msg before fp32 overlay
#pragma unroll
            for (int mt = 0; mt < 2; mt++) {
                const int r0 = lr + mt * 16;
#pragma unroll
                for (int jh = 0; jh < 4; jh++) {
                    const int ai = mt * 4 + jh;
                    const int col = cBase + jh * 8 + q2;
                    *reinterpret_cast<float2*>(s_outF + r0 * OUT_STRIDE + col) =
                        make_float2(tanh_fast(acc[ai][0]), tanh_fast(acc[ai][1]));
                    *reinterpret_cast<float2*>(s_outF + (r0 + 8) * OUT_STRIDE + col) =
                        make_float2(tanh_fast(acc[ai][2]), tanh_fast(acc[ai][3]));
                }
            }
            barh(bar_id);
            // run-length segment reduction (dmi sorted): ~1 atomic per run
            const int c = lt & 127;
            const int r0 = (lt >> 7) << 5;   // 2 segments x 32 rows
            float racc = 0.f;
            int cur = s_dmi[r0];
            for (int rr = r0; rr < r0 + 32; rr++) {
                const int ir = s_dmi[rr];
                if (ir != cur) {
                    atomicAdd(out + (size_t)cur * 128 + c, racc);
                    racc = 0.f;
                    cur = ir;
                }
                racc += s_outF[rr * OUT_STRIDE + c];
            }
            atomicAdd(out + (size_t)cur * 128 + c, racc);
        }
    }
}

// ---------------------------------------------------------------------------
extern "C" void kernel_launch(void* const* d_in, const int* in_sizes, int n_in,
                              void* d_out, int out_size)
{
    const float* atom_features = (const float*)d_in[0];
    const float* distance      = (const float*)d_in[1];
    // d_in[2] = atom_membership (unused by the computation)
    const int*   dmi           = (const int*)d_in[3];
    const int*   dmj           = (const int*)d_in[4];
    const float* W_cf          = (const float*)d_in[5];
    const float* W_df          = (const float*)d_in[6];
    const float* W_fc          = (const float*)d_in[7];
    const float* b_cf          = (const float*)d_in[8];
    const float* b_df          = (const float*)d_in[9];
    float* out = (float*)d_out;

    float* afh = nullptr;
    cudaGetSymbolAddress((void**)&afh, g_afh);

    cudaFuncSetAttribute(dtnn_mma<false, 128>,
                         cudaFuncAttributeMaxDynamicSharedMemorySize, SMEM_SZ);
    cudaFuncSetAttribute(dtnn_mma<true, 100>,
                         cudaFuncAttributeMaxDynamicSharedMemorySize, SMEM_SZ);

    const int atom_tiles = (N_ATOMS + 63) / 64;   // 782 (64-row tiles)
    const int pair_tiles = N_PAIRS / 64;          // 12500

    // 1. Atom path: afh + out init (writes every output element)
    dtnn_mma<false, 128><<<152, THREADS, SMEM_SZ>>>(
        atom_features, W_cf, W_fc, b_cf, b_df, afh, nullptr, nullptr,
        out, N_ATOMS, atom_tiles);

    // 2. Pair path: msgs + run-length-reduced segment sum
    dtnn_mma<true, 100><<<152, THREADS, SMEM_SZ>>>(
        distance, W_df, W_fc, b_df, nullptr, afh, dmj, dmi,
        out, N_PAIRS, pair_tiles);
}